// round 4
// baseline (speedup 1.0000x reference)
#include <cuda_runtime.h>
#include <stdint.h>

#define OFF_LOGP 0
#define OFF_SD   6336
#define OFF_GD   6400
#define OFF_PRED 6464
#define OFF_GSOL 1286464

__device__ float g_buf0[819200];
__device__ float g_buf1[819200];
__device__ float g_hWs[819200];
__device__ float g_hN[819200];
__device__ float g_A[640000];
__device__ float g_gum[633600];   // 99 * 6400
__device__ int   g_solg[6400];

// ---------------- threefry2x32 (exact JAX) ----------------
__device__ __forceinline__ void tf2x32(uint32_t k0, uint32_t k1,
                                       uint32_t c0, uint32_t c1,
                                       uint32_t& o0, uint32_t& o1) {
  uint32_t ks0 = k0, ks1 = k1, ks2 = k0 ^ k1 ^ 0x1BD11BDAu;
  uint32_t x0 = c0 + ks0, x1 = c1 + ks1;
#define TF_RND(R) { x0 += x1; x1 = __funnelshift_l(x1, x1, (R)); x1 ^= x0; }
  TF_RND(13) TF_RND(15) TF_RND(26) TF_RND(6)   x0 += ks1; x1 += ks2 + 1u;
  TF_RND(17) TF_RND(29) TF_RND(16) TF_RND(24)  x0 += ks2; x1 += ks0 + 2u;
  TF_RND(13) TF_RND(15) TF_RND(26) TF_RND(6)   x0 += ks0; x1 += ks1 + 3u;
  TF_RND(17) TF_RND(29) TF_RND(16) TF_RND(24)  x0 += ks1; x1 += ks2 + 4u;
  TF_RND(13) TF_RND(15) TF_RND(26) TF_RND(6)   x0 += ks2; x1 += ks0 + 5u;
#undef TF_RND
  o0 = x0; o1 = x1;
}

// ---------------- h0 = relu([node,demand] @ Wn0 + bn0) ----------------
__global__ void k_h0(const float* __restrict__ node, const float* __restrict__ demand,
                     const float* __restrict__ Wn0, const float* __restrict__ bn0) {
  int idx = blockIdx.x * blockDim.x + threadIdx.x;
  if (idx >= 819200) return;
  int row = idx >> 7, j = idx & 127;
  float v = bn0[j];
  v = fmaf(node[row * 2],     Wn0[j],       v);
  v = fmaf(node[row * 2 + 1], Wn0[128 + j], v);
  v = fmaf(demand[row],       Wn0[256 + j], v);
  g_buf0[idx] = fmaxf(v, 0.f);
}

// ---------------- A = softmax(-dis, -1), warp per row ----------------
__global__ void k_softA(const float* __restrict__ dis) {
  int row  = blockIdx.x * 4 + (threadIdx.x >> 5);
  int lane = threadIdx.x & 31;
  if (row >= 6400) return;
  const float* d = dis + row * 100;
  float v0 = -d[lane], v1 = -d[lane + 32], v2 = -d[lane + 64];
  float v3 = (lane + 96 < 100) ? -d[lane + 96] : -3.4e38f;
  float m = fmaxf(fmaxf(v0, v1), fmaxf(v2, v3));
#pragma unroll
  for (int o = 16; o > 0; o >>= 1) m = fmaxf(m, __shfl_xor_sync(0xffffffffu, m, o));
  float e0 = expf(v0 - m), e1 = expf(v1 - m), e2 = expf(v2 - m);
  float e3 = (lane + 96 < 100) ? expf(v3 - m) : 0.f;
  float s = e0 + e1 + e2 + e3;
#pragma unroll
  for (int o = 16; o > 0; o >>= 1) s += __shfl_xor_sync(0xffffffffu, s, o);
  float* Ar = g_A + row * 100;
  Ar[lane] = e0 / s; Ar[lane + 32] = e1 / s; Ar[lane + 64] = e2 / s;
  if (lane + 96 < 100) Ar[lane + 96] = e3 / s;
}

// ---------------- hWs = h@Ws[l], hN = h@Wngh[l]; 8 rows per block ----------------
__global__ void k_gemm2(int src, const float* __restrict__ W1, const float* __restrict__ W2) {
  const float* h = src ? g_buf1 : g_buf0;
  __shared__ float acts[8][128];
  int j = threadIdx.x;
  int row0 = blockIdx.x * 8;
#pragma unroll
  for (int r = 0; r < 8; r++) acts[r][j] = h[(row0 + r) * 128 + j];
  __syncthreads();
  float aS[8], aN[8];
#pragma unroll
  for (int r = 0; r < 8; r++) { aS[r] = 0.f; aN[r] = 0.f; }
#pragma unroll 4
  for (int k = 0; k < 128; k++) {
    float ws = __ldg(W1 + k * 128 + j);
    float wn = __ldg(W2 + k * 128 + j);
#pragma unroll
    for (int r = 0; r < 8; r++) {
      float a = acts[r][k];
      aS[r] = fmaf(a, ws, aS[r]);
      aN[r] = fmaf(a, wn, aN[r]);
    }
  }
#pragma unroll
  for (int r = 0; r < 8; r++) {
    g_hWs[(row0 + r) * 128 + j] = aS[r];
    g_hN [(row0 + r) * 128 + j] = aN[r];
  }
}

// ---------------- h_next = relu(hWs + A @ hN), block per batch ----------------
__global__ void k_aggr(int dst) {
  extern __shared__ float sm[];
  float* hN_s = sm;            // [100][128]
  float* A_s  = sm + 12800;    // [100][100]
  int b = blockIdx.x, tid = threadIdx.x;
  for (int i = tid; i < 12800; i += 256) hN_s[i] = g_hN[b * 12800 + i];
  for (int i = tid; i < 10000; i += 256) A_s[i]  = g_A [b * 10000 + i];
  __syncthreads();
  float* ho = dst ? g_buf1 : g_buf0;
  int g = tid >> 7, j = tid & 127;
  for (int i = g; i < 100; i += 2) {
    float a0 = 0.f, a1 = 0.f;
#pragma unroll 10
    for (int p = 0; p < 100; p += 2) {
      a0 = fmaf(A_s[i * 100 + p],     hN_s[p * 128 + j],       a0);
      a1 = fmaf(A_s[i * 100 + p + 1], hN_s[(p + 1) * 128 + j], a1);
    }
    float v = g_hWs[(b * 100 + i) * 128 + j] + a0 + a1;
    ho[(b * 100 + i) * 128 + j] = fmaxf(v, 0.f);
  }
}

// ---------------- gumbel precompute: block t handles step t ----------------
__global__ void k_gumbel() {
  int t = blockIdx.x;  // 0..98
  __shared__ uint32_t sk0, sk1;
  if (threadIdx.x == 0) {
    // key(42) = (0,42); k1 = split(root)[0] = TF(root,(0,0))
    uint32_t k0 = 0u, k1 = 42u, a, b;
    tf2x32(k0, k1, 0u, 0u, a, b); k0 = a; k1 = b;
    for (int i = 0; i < t; i++) { tf2x32(k0, k1, 0u, 0u, a, b); k0 = a; k1 = b; }
    tf2x32(k0, k1, 0u, 1u, a, b); sk0 = a; sk1 = b;   // sk = split(k)[1]
  }
  __syncthreads();
  const float TINY = 1.17549435e-38f;
  uint32_t s0 = sk0, s1 = sk1;
  for (int i = threadIdx.x; i < 6400; i += blockDim.x) {
    uint32_t o0, o1;
    tf2x32(s0, s1, 0u, (uint32_t)i, o0, o1);
    uint32_t bits = o0 ^ o1;
    float f = __uint_as_float((bits >> 9) | 0x3f800000u) - 1.0f;
    float u = fmaxf(TINY, f + TINY);
    g_gum[t * 6400 + i] = -logf(-logf(u));
  }
}

__device__ __forceinline__ float sigm(float x) { return 1.f / (1.f + expf(-x)); }

// ---------------- fused dual-stream decoder, block per batch ----------------
#define DEC_FLOATS 33888
__global__ void __launch_bounds__(384, 1) k_decode(
    const float* __restrict__ dis, const float* __restrict__ Wih,
    const float* __restrict__ Whh, const float* __restrict__ bih,
    const float* __restrict__ bhh, const float* __restrict__ Wq,
    float* __restrict__ out) {
  extern __shared__ float sm[];
  const int tid = threadIdx.x, b = blockIdx.x;
  float*  x_s  = sm;                      // [100][129]
  float*  wq_s = sm + 12900;              // [128][128]
  float*  bi0  = sm + 29284;
  float*  bh0  = sm + 29668;
  float*  bi1  = sm + 30052;
  float*  bh1  = sm + 30436;
  float2* gi2  = (float2*)(sm + 30820);   // [384]
  float2* gh2  = (float2*)(sm + 31588);   // [384]
  float2* emb2 = (float2*)(sm + 32356);   // [128]
  float2* h0s  = (float2*)(sm + 32612);
  float2* h1s  = (float2*)(sm + 32868);
  float2* q2   = (float2*)(sm + 33124);
  float*  ls   = sm + 33380;
  float*  lg   = sm + 33480;
  float*  ys   = sm + 33580;
  float*  red  = sm + 33680;              // 4 floats
  int*    sol_s = (int*)(sm + 33684);
  int*    sol_g = (int*)(sm + 33784);
  int*    sh_i  = (int*)(sm + 33884);

  for (int i = tid; i < 12800; i += 384) {
    int r = i >> 7, c = i & 127;
    x_s[r * 129 + c] = g_buf1[(b * 100 + r) * 128 + c];
  }
  for (int i = tid; i < 16384; i += 384) wq_s[i] = Wq[i];
  bi0[tid] = bih[tid];       bh0[tid] = bhh[tid];
  bi1[tid] = bih[384 + tid]; bh1[tid] = bhh[384 + tid];
  if (tid < 128) { h0s[tid] = make_float2(0.f, 0.f); h1s[tid] = make_float2(0.f, 0.f); }
  if (tid == 0)  { sol_s[0] = 0; sol_g[0] = 0; }
  __syncthreads();
  if (tid < 128) { float v = x_s[tid]; emb2[tid] = make_float2(v, v); }
  __syncthreads();

  const float scale = (float)(1.0 / (double)sqrtf(128.0f));
  const float* Wi0 = Wih;          const float* Wh0 = Whh;
  const float* Wi1 = Wih + 49152;  const float* Wh1 = Whh + 49152;
  const int lane = tid & 31, wrp = tid >> 5;

  for (int t = 0; t < 99; t++) {
    // ---- layer 0 gate gemv (both streams) ----
    {
      float gis = bi0[tid], gig = gis, ghs = bh0[tid], ghg = ghs;
#pragma unroll 4
      for (int k = 0; k < 128; k++) {
        float wi = __ldg(Wi0 + k * 384 + tid), wh = __ldg(Wh0 + k * 384 + tid);
        float2 e = emb2[k], h = h0s[k];
        gis = fmaf(e.x, wi, gis); gig = fmaf(e.y, wi, gig);
        ghs = fmaf(h.x, wh, ghs); ghg = fmaf(h.y, wh, ghg);
      }
      gi2[tid] = make_float2(gis, gig); gh2[tid] = make_float2(ghs, ghg);
    }
    __syncthreads();
    if (tid < 128) {
      float2 ir = gi2[tid], iz = gi2[tid + 128], in_ = gi2[tid + 256];
      float2 hr = gh2[tid], hz = gh2[tid + 128], hn  = gh2[tid + 256];
      float2 hp = h0s[tid];
      float r0 = sigm(ir.x + hr.x), z0 = sigm(iz.x + hz.x), n0 = tanhf(in_.x + r0 * hn.x);
      float r1 = sigm(ir.y + hr.y), z1 = sigm(iz.y + hz.y), n1 = tanhf(in_.y + r1 * hn.y);
      h0s[tid] = make_float2((1.f - z0) * n0 + z0 * hp.x, (1.f - z1) * n1 + z1 * hp.y);
    }
    __syncthreads();
    // ---- layer 1 gate gemv ----
    {
      float gis = bi1[tid], gig = gis, ghs = bh1[tid], ghg = ghs;
#pragma unroll 4
      for (int k = 0; k < 128; k++) {
        float wi = __ldg(Wi1 + k * 384 + tid), wh = __ldg(Wh1 + k * 384 + tid);
        float2 e = h0s[k], h = h1s[k];
        gis = fmaf(e.x, wi, gis); gig = fmaf(e.y, wi, gig);
        ghs = fmaf(h.x, wh, ghs); ghg = fmaf(h.y, wh, ghg);
      }
      gi2[tid] = make_float2(gis, gig); gh2[tid] = make_float2(ghs, ghg);
    }
    __syncthreads();
    if (tid < 128) {
      float2 ir = gi2[tid], iz = gi2[tid + 128], in_ = gi2[tid + 256];
      float2 hr = gh2[tid], hz = gh2[tid + 128], hn  = gh2[tid + 256];
      float2 hp = h1s[tid];
      float r0 = sigm(ir.x + hr.x), z0 = sigm(iz.x + hz.x), n0 = tanhf(in_.x + r0 * hn.x);
      float r1 = sigm(ir.y + hr.y), z1 = sigm(iz.y + hz.y), n1 = tanhf(in_.y + r1 * hn.y);
      h1s[tid] = make_float2((1.f - z0) * n0 + z0 * hp.x, (1.f - z1) * n1 + z1 * hp.y);
    }
    __syncthreads();
    // ---- q = h1 @ Wq ----
    if (tid < 128) {
      float qs = 0.f, qg = 0.f;
#pragma unroll 4
      for (int k = 0; k < 128; k++) {
        float w = wq_s[k * 128 + tid]; float2 h = h1s[k];
        qs = fmaf(h.x, w, qs); qg = fmaf(h.y, w, qg);
      }
      q2[tid] = make_float2(qs, qg);
    }
    __syncthreads();
    // ---- logits: 12 warps over 100 nodes ----
    for (int i = wrp; i < 100; i += 12) {
      float ssx = 0.f, ggx = 0.f;
#pragma unroll
      for (int r = 0; r < 4; r++) {
        int k = lane + 32 * r;
        float2 q = q2[k]; float xv = x_s[i * 129 + k];
        ssx = fmaf(q.x, xv, ssx); ggx = fmaf(q.y, xv, ggx);
      }
#pragma unroll
      for (int o = 16; o > 0; o >>= 1) {
        ssx += __shfl_xor_sync(0xffffffffu, ssx, o);
        ggx += __shfl_xor_sync(0xffffffffu, ggx, o);
      }
      if (lane == 0) {
        float lsv = ssx * scale;
        ls[i] = lsv;
        ys[i] = lsv + g_gum[t * 6400 + b * 100 + i];
        lg[i] = ggx * scale;
      }
    }
    __syncthreads();
    // ---- reductions ----
    if (wrp == 0) {            // argmax(ys) -> sample index
      float bv = -3.4e38f; int bi_ = 0;
#pragma unroll
      for (int r = 0; r < 4; r++) { int i = lane + 32 * r; if (i < 100) { float v = ys[i]; if (v > bv) { bv = v; bi_ = i; } } }
#pragma unroll
      for (int o = 16; o > 0; o >>= 1) {
        float ov = __shfl_xor_sync(0xffffffffu, bv, o);
        int   oi = __shfl_xor_sync(0xffffffffu, bi_, o);
        if (ov > bv || (ov == bv && oi < bi_)) { bv = ov; bi_ = oi; }
      }
      if (lane == 0) sh_i[0] = bi_;
    } else if (wrp == 1) {     // argmax(lg) -> greedy index
      float bv = -3.4e38f; int bi_ = 0;
#pragma unroll
      for (int r = 0; r < 4; r++) { int i = lane + 32 * r; if (i < 100) { float v = lg[i]; if (v > bv) { bv = v; bi_ = i; } } }
#pragma unroll
      for (int o = 16; o > 0; o >>= 1) {
        float ov = __shfl_xor_sync(0xffffffffu, bv, o);
        int   oi = __shfl_xor_sync(0xffffffffu, bi_, o);
        if (ov > bv || (ov == bv && oi < bi_)) { bv = ov; bi_ = oi; }
      }
      if (lane == 0) sh_i[1] = bi_;
    } else if (wrp == 2) {     // max(ls)
      float m = -3.4e38f;
#pragma unroll
      for (int r = 0; r < 4; r++) { int i = lane + 32 * r; if (i < 100) m = fmaxf(m, ls[i]); }
#pragma unroll
      for (int o = 16; o > 0; o >>= 1) m = fmaxf(m, __shfl_xor_sync(0xffffffffu, m, o));
      if (lane == 0) red[0] = m;
    }
    __syncthreads();
    if (wrp == 2) {            // logsumexp + write logp + record solutions
      float m = red[0], s = 0.f;
#pragma unroll
      for (int r = 0; r < 4; r++) { int i = lane + 32 * r; if (i < 100) s += expf(ls[i] - m); }
#pragma unroll
      for (int o = 16; o > 0; o >>= 1) s += __shfl_xor_sync(0xffffffffu, s, o);
      if (lane == 0) {
        int is_ = sh_i[0], ig_ = sh_i[1];
        out[OFF_LOGP + b * 99 + t] = ls[is_] - m - logf(s);
        sol_s[t + 1] = is_; sol_g[t + 1] = ig_;
      }
    }
    __syncthreads();
    if (tid < 128) {
      int is_ = sh_i[0], ig_ = sh_i[1];
      emb2[tid] = make_float2(x_s[is_ * 129 + tid], x_s[ig_ * 129 + tid]);
    }
    __syncthreads();
  }
  // ---- epilogue: distances + greedy solution export ----
  if (tid == 0) { red[2] = 0.f; red[3] = 0.f; }
  __syncthreads();
  if (tid < 99) {
    atomicAdd(&red[2], dis[b * 10000 + sol_s[tid] * 100 + sol_s[tid + 1]]);
    atomicAdd(&red[3], dis[b * 10000 + sol_g[tid] * 100 + sol_g[tid + 1]]);
  }
  for (int i = tid; i < 100; i += 384) g_solg[b * 100 + i] = sol_g[i];
  __syncthreads();
  if (tid == 0) { out[OFF_SD + b] = red[2]; out[OFF_GD + b] = red[3]; }
}

// ---------------- predict_matrix fused, warp per (b,i,j) ----------------
__global__ void k_pred(const float* __restrict__ dis, const float* __restrict__ We,
                       const float* __restrict__ be, const float* __restrict__ Wc,
                       const float* __restrict__ bc, float* __restrict__ out) {
  int lane = threadIdx.x & 31;
  int gw = (blockIdx.x * blockDim.x + threadIdx.x) >> 5;
  int nw = (gridDim.x * blockDim.x) >> 5;
  float we[4], bee[4], wc0[4], wc1[4];
#pragma unroll
  for (int u = 0; u < 4; u++) {
    int k = lane * 4 + u;
    we[u] = We[k]; bee[u] = be[k]; wc0[u] = Wc[k * 2]; wc1[u] = Wc[k * 2 + 1];
  }
  float bc0 = bc[0], bc1 = bc[1];
  for (int p = gw; p < 640000; p += nw) {
    float d = dis[p];
    float y0 = 0.f, y1 = 0.f;
#pragma unroll
    for (int u = 0; u < 4; u++) {
      float e = fmaxf(fmaf(d, we[u], bee[u]), 0.f);
      y0 = fmaf(e, wc0[u], y0); y1 = fmaf(e, wc1[u], y1);
    }
#pragma unroll
    for (int o = 16; o > 0; o >>= 1) {
      y0 += __shfl_xor_sync(0xffffffffu, y0, o);
      y1 += __shfl_xor_sync(0xffffffffu, y1, o);
    }
    if (lane == 0) {
      y0 += bc0; y1 += bc1;
      float m = fmaxf(y0, y1);
      float e0 = expf(y0 - m), e1 = expf(y1 - m), s = e0 + e1;
      out[OFF_PRED + p * 2]     = e0 / s;
      out[OFF_PRED + p * 2 + 1] = e1 / s;
    }
  }
}

__global__ void k_gzero(float* __restrict__ out) {
  int idx = blockIdx.x * blockDim.x + threadIdx.x;
  if (idx < 640000) out[OFF_GSOL + idx] = 0.f;
}

__global__ void k_gset(float* __restrict__ out) {
  int b = blockIdx.x, t = threadIdx.x;
  if (t < 99) {
    int u = g_solg[b * 100 + t], v = g_solg[b * 100 + t + 1];
    out[OFF_GSOL + b * 10000 + u * 100 + v] = 1.0f;
  }
}

extern "C" void kernel_launch(void* const* d_in, const int* in_sizes, int n_in,
                              void* d_out, int out_size) {
  const float* node   = (const float*)d_in[0];
  const float* demand = (const float*)d_in[1];
  const float* dis    = (const float*)d_in[2];
  const float* Wn0    = (const float*)d_in[3];
  const float* bn0    = (const float*)d_in[4];
  const float* Ws     = (const float*)d_in[5];
  const float* Wngh   = (const float*)d_in[6];
  const float* We     = (const float*)d_in[7];
  const float* be     = (const float*)d_in[8];
  const float* Wih    = (const float*)d_in[9];
  const float* Whh    = (const float*)d_in[10];
  const float* bih    = (const float*)d_in[11];
  const float* bhh    = (const float*)d_in[12];
  const float* Wq     = (const float*)d_in[13];
  const float* Wc     = (const float*)d_in[14];
  const float* bc     = (const float*)d_in[15];
  float* out = (float*)d_out;

  cudaFuncSetAttribute(k_aggr,   cudaFuncAttributeMaxDynamicSharedMemorySize, 91200);
  cudaFuncSetAttribute(k_decode, cudaFuncAttributeMaxDynamicSharedMemorySize, DEC_FLOATS * 4);

  k_h0<<<3200, 256>>>(node, demand, Wn0, bn0);
  k_softA<<<1600, 128>>>(dis);
  int src = 0;
  for (int l = 0; l < 3; l++) {
    k_gemm2<<<800, 128>>>(src, Ws + l * 16384, Wngh + l * 16384);
    int dst = 1 - src;
    k_aggr<<<64, 256, 91200>>>(dst);
    src = dst;
  }
  // src == 1 here: final h lives in g_buf1 (decoder reads g_buf1)
  k_gumbel<<<99, 256>>>();
  k_decode<<<64, 384, DEC_FLOATS * 4>>>(dis, Wih, Whh, bih, bhh, Wq, out);
  k_pred<<<1280, 256>>>(dis, We, be, Wc, bc, out);
  k_gzero<<<2500, 256>>>(out);
  k_gset<<<64, 128>>>(out);
}

// round 5
// speedup vs baseline: 2.8026x; 2.8026x over previous
#include <cuda_runtime.h>
#include <stdint.h>

#define OFF_LOGP 0
#define OFF_SD   6336
#define OFF_GD   6400
#define OFF_PRED 6464
#define OFF_GSOL 1286464

__device__ float g_buf0[819200];
__device__ float g_buf1[819200];
__device__ float g_hWs[819200];
__device__ float g_hN[819200];
__device__ float g_A[640000];
__device__ float g_gum[633600];    // 99 * 6400
__device__ int   g_solg[6400];
__device__ float g_gi0[2457600];   // [64][100][384] precomputed x@Wih0+bih0
__device__ float g_y[819200];      // [64][100][128] precomputed x@Wq^T
__device__ float4 g_wpack4[36864]; // packed Wh0,Wi1,Wh1: [(m*32+kk)*384+o] -> k=4kk+u

// ---------------- threefry2x32 (exact JAX) ----------------
__device__ __forceinline__ void tf2x32(uint32_t k0, uint32_t k1,
                                       uint32_t c0, uint32_t c1,
                                       uint32_t& o0, uint32_t& o1) {
  uint32_t ks0 = k0, ks1 = k1, ks2 = k0 ^ k1 ^ 0x1BD11BDAu;
  uint32_t x0 = c0 + ks0, x1 = c1 + ks1;
#define TF_RND(R) { x0 += x1; x1 = __funnelshift_l(x1, x1, (R)); x1 ^= x0; }
  TF_RND(13) TF_RND(15) TF_RND(26) TF_RND(6)   x0 += ks1; x1 += ks2 + 1u;
  TF_RND(17) TF_RND(29) TF_RND(16) TF_RND(24)  x0 += ks2; x1 += ks0 + 2u;
  TF_RND(13) TF_RND(15) TF_RND(26) TF_RND(6)   x0 += ks0; x1 += ks1 + 3u;
  TF_RND(17) TF_RND(29) TF_RND(16) TF_RND(24)  x0 += ks1; x1 += ks2 + 4u;
  TF_RND(13) TF_RND(15) TF_RND(26) TF_RND(6)   x0 += ks2; x1 += ks0 + 5u;
#undef TF_RND
  o0 = x0; o1 = x1;
}

// ---------------- h0 = relu([node,demand] @ Wn0 + bn0) ----------------
__global__ void k_h0(const float* __restrict__ node, const float* __restrict__ demand,
                     const float* __restrict__ Wn0, const float* __restrict__ bn0) {
  int idx = blockIdx.x * blockDim.x + threadIdx.x;
  if (idx >= 819200) return;
  int row = idx >> 7, j = idx & 127;
  float v = bn0[j];
  v = fmaf(node[row * 2],     Wn0[j],       v);
  v = fmaf(node[row * 2 + 1], Wn0[128 + j], v);
  v = fmaf(demand[row],       Wn0[256 + j], v);
  g_buf0[idx] = fmaxf(v, 0.f);
}

// ---------------- A = softmax(-dis, -1), warp per row ----------------
__global__ void k_softA(const float* __restrict__ dis) {
  int row  = blockIdx.x * 4 + (threadIdx.x >> 5);
  int lane = threadIdx.x & 31;
  if (row >= 6400) return;
  const float* d = dis + row * 100;
  float v0 = -d[lane], v1 = -d[lane + 32], v2 = -d[lane + 64];
  float v3 = (lane + 96 < 100) ? -d[lane + 96] : -3.4e38f;
  float m = fmaxf(fmaxf(v0, v1), fmaxf(v2, v3));
#pragma unroll
  for (int o = 16; o > 0; o >>= 1) m = fmaxf(m, __shfl_xor_sync(0xffffffffu, m, o));
  float e0 = expf(v0 - m), e1 = expf(v1 - m), e2 = expf(v2 - m);
  float e3 = (lane + 96 < 100) ? expf(v3 - m) : 0.f;
  float s = e0 + e1 + e2 + e3;
#pragma unroll
  for (int o = 16; o > 0; o >>= 1) s += __shfl_xor_sync(0xffffffffu, s, o);
  float* Ar = g_A + row * 100;
  Ar[lane] = e0 / s; Ar[lane + 32] = e1 / s; Ar[lane + 64] = e2 / s;
  if (lane + 96 < 100) Ar[lane + 96] = e3 / s;
}

// ---------------- hWs = h@Ws[l], hN = h@Wngh[l]; 8 rows per block ----------------
__global__ void k_gemm2(int src, const float* __restrict__ W1, const float* __restrict__ W2) {
  const float* h = src ? g_buf1 : g_buf0;
  __shared__ float acts[8][128];
  int j = threadIdx.x;
  int row0 = blockIdx.x * 8;
#pragma unroll
  for (int r = 0; r < 8; r++) acts[r][j] = h[(row0 + r) * 128 + j];
  __syncthreads();
  float aS[8], aN[8];
#pragma unroll
  for (int r = 0; r < 8; r++) { aS[r] = 0.f; aN[r] = 0.f; }
#pragma unroll 8
  for (int k = 0; k < 128; k++) {
    float ws = __ldg(W1 + k * 128 + j);
    float wn = __ldg(W2 + k * 128 + j);
#pragma unroll
    for (int r = 0; r < 8; r++) {
      float a = acts[r][k];
      aS[r] = fmaf(a, ws, aS[r]);
      aN[r] = fmaf(a, wn, aN[r]);
    }
  }
#pragma unroll
  for (int r = 0; r < 8; r++) {
    g_hWs[(row0 + r) * 128 + j] = aS[r];
    g_hN [(row0 + r) * 128 + j] = aN[r];
  }
}

// ---------------- h_next = relu(hWs + A @ hN); grid (64,4), 25 rows/block ----------------
#define AGGR2_SMEM ((12800 + 2500) * 4)
__global__ void k_aggr(int dst) {
  extern __shared__ float sm[];
  float* hN_s = sm;            // [100][128]
  float* A_s  = sm + 12800;    // [25][100]
  int b = blockIdx.x, r0 = blockIdx.y * 25, tid = threadIdx.x;
  for (int i = tid; i < 12800; i += 256) hN_s[i] = g_hN[b * 12800 + i];
  for (int i = tid; i < 2500; i += 256)  A_s[i]  = g_A [b * 10000 + r0 * 100 + i];
  __syncthreads();
  float* ho = dst ? g_buf1 : g_buf0;
  int j = tid & 127, g = tid >> 7;
  for (int il = g; il < 25; il += 4) {
    int i2 = il + 2;
    bool two = i2 < 25;
    float a0 = 0.f, a1 = 0.f, c0 = 0.f, c1 = 0.f;
#pragma unroll 10
    for (int p = 0; p < 100; p += 2) {
      float h0v = hN_s[p * 128 + j], h1v = hN_s[(p + 1) * 128 + j];
      a0 = fmaf(A_s[il * 100 + p],     h0v, a0);
      a1 = fmaf(A_s[il * 100 + p + 1], h1v, a1);
      if (two) {
        c0 = fmaf(A_s[i2 * 100 + p],     h0v, c0);
        c1 = fmaf(A_s[i2 * 100 + p + 1], h1v, c1);
      }
    }
    int row = b * 100 + r0 + il;
    ho[row * 128 + j] = fmaxf(g_hWs[row * 128 + j] + a0 + a1, 0.f);
    if (two)
      ho[(row + 2) * 128 + j] = fmaxf(g_hWs[(row + 2) * 128 + j] + c0 + c1, 0.f);
  }
}

// ---------------- precompute Gi0 = x @ Wih0 + bih0 ; 8 rows/block, 384 threads ----------------
__global__ void k_gi0(const float* __restrict__ Wih, const float* __restrict__ bih) {
  __shared__ float acts[8][128];
  int o = threadIdx.x;
  int row0 = blockIdx.x * 8;
  for (int i = o; i < 1024; i += 384) acts[i >> 7][i & 127] = g_buf1[row0 * 128 + i];
  __syncthreads();
  float a[8];
  float bv = bih[o];
#pragma unroll
  for (int r = 0; r < 8; r++) a[r] = bv;
#pragma unroll 8
  for (int k = 0; k < 128; k++) {
    float w = __ldg(Wih + k * 384 + o);
#pragma unroll
    for (int r = 0; r < 8; r++) a[r] = fmaf(acts[r][k], w, a[r]);
  }
#pragma unroll
  for (int r = 0; r < 8; r++) g_gi0[(row0 + r) * 384 + o] = a[r];
}

// ---------------- precompute Y[b,i,k] = sum_j Wq[k,j]*x[b,i,j] ; 8 rows/block ----------------
#define Y_SMEM ((129 * 128 + 1024) * 4)
__global__ void k_y(const float* __restrict__ Wq) {
  extern __shared__ float sm[];
  float* wq_t = sm;            // [j][k] padded 129
  float* acts = sm + 16512;    // [8][128]
  int tid = threadIdx.x;
  int row0 = blockIdx.x * 8;
  for (int i = tid; i < 16384; i += 128) {
    int k = i >> 7, j = i & 127;
    wq_t[j * 129 + k] = Wq[i];
  }
  for (int i = tid; i < 1024; i += 128) acts[i] = g_buf1[row0 * 128 + i];
  __syncthreads();
  int k = tid;
  float a[8];
#pragma unroll
  for (int r = 0; r < 8; r++) a[r] = 0.f;
#pragma unroll 4
  for (int j = 0; j < 128; j++) {
    float w = wq_t[j * 129 + k];
#pragma unroll
    for (int r = 0; r < 8; r++) a[r] = fmaf(acts[r * 128 + j], w, a[r]);
  }
#pragma unroll
  for (int r = 0; r < 8; r++) g_y[(row0 + r) * 128 + k] = a[r];
}

// ---------------- pack Wh0, Wi1, Wh1 into float4-friendly layout ----------------
__global__ void k_pack(const float* __restrict__ Wih, const float* __restrict__ Whh) {
  int idx = blockIdx.x * blockDim.x + threadIdx.x;
  if (idx >= 147456) return;
  int m = idx / 49152, r = idx % 49152;
  int t4 = r >> 2, u = r & 3;
  int o = t4 % 384, kk = t4 / 384;
  int k = kk * 4 + u;
  const float* src = (m == 0) ? Whh : (m == 1 ? (Wih + 49152) : (Whh + 49152));
  ((float*)g_wpack4)[idx] = src[k * 384 + o];
}

// ---------------- gumbel precompute: block t handles step t ----------------
__global__ void k_gumbel() {
  int t = blockIdx.x;
  __shared__ uint32_t sk0, sk1;
  if (threadIdx.x == 0) {
    uint32_t k0 = 0u, k1 = 42u, a, b;
    tf2x32(k0, k1, 0u, 0u, a, b); k0 = a; k1 = b;
    for (int i = 0; i < t; i++) { tf2x32(k0, k1, 0u, 0u, a, b); k0 = a; k1 = b; }
    tf2x32(k0, k1, 0u, 1u, a, b); sk0 = a; sk1 = b;
  }
  __syncthreads();
  const float TINY = 1.17549435e-38f;
  uint32_t s0 = sk0, s1 = sk1;
  for (int i = threadIdx.x; i < 6400; i += blockDim.x) {
    uint32_t o0, o1;
    tf2x32(s0, s1, 0u, (uint32_t)i, o0, o1);
    uint32_t bits = o0 ^ o1;
    float f = __uint_as_float((bits >> 9) | 0x3f800000u) - 1.0f;
    float u = fmaxf(TINY, f + TINY);
    g_gum[t * 6400 + i] = -logf(-logf(u));
  }
}

__device__ __forceinline__ float sigm(float x) { return 1.f / (1.f + expf(-x)); }

// ---------------- fused dual-stream decoder (uses Gi0, Y, packed weights) ----------------
#define DEC_FLOATS 16606
__global__ void __launch_bounds__(384, 1) k_decode(
    const float* __restrict__ dis, const float* __restrict__ bih,
    const float* __restrict__ bhh, float* __restrict__ out) {
  extern __shared__ float sm[];
  const int tid = threadIdx.x, b = blockIdx.x;
  const int lane = tid & 31, wrp = tid >> 5;

  float*  Y_s  = sm;                      // [100][128]
  float*  bh0s = sm + 12800;              // [384]
  float*  bi1s = sm + 13184;
  float*  bh1s = sm + 13568;
  float2* gi2  = (float2*)(sm + 13952);   // [384]
  float2* gh2  = (float2*)(sm + 14720);   // [384]
  float2* h0s  = (float2*)(sm + 15488);   // [128]
  float2* h1s  = (float2*)(sm + 15744);   // [128]
  float*  gums = sm + 16000;              // [100]
  float*  ls   = sm + 16100;
  float*  lg   = sm + 16200;
  float*  ys   = sm + 16300;
  float*  red  = sm + 16400;              // [4]
  int*    sol_s = (int*)(sm + 16404);     // [100]
  int*    sol_g = (int*)(sm + 16504);     // [100]
  int*    sh_i  = (int*)(sm + 16604);     // [2]

  for (int i = tid; i < 12800; i += 384) Y_s[i] = g_y[b * 12800 + i];
  bh0s[tid] = bhh[tid];
  bi1s[tid] = bih[384 + tid];
  bh1s[tid] = bhh[384 + tid];
  if (tid < 128) { h0s[tid] = make_float2(0.f, 0.f); h1s[tid] = make_float2(0.f, 0.f); }
  if (tid == 0)  { sol_s[0] = 0; sol_g[0] = 0; }
  __syncthreads();

  const float scale = (float)(1.0 / (double)sqrtf(128.0f));
  const float4* Wp0 = g_wpack4;            // Wh0
  const float4* Wp1 = g_wpack4 + 12288;    // Wi1
  const float4* Wp2 = g_wpack4 + 24576;    // Wh1

  for (int t = 0; t < 99; t++) {
    // prefetch gumbel for this step (warp 11)
    if (wrp == 11)
      for (int i = lane; i < 100; i += 32) gums[i] = g_gum[t * 6400 + b * 100 + i];
    // stage layer-0 input gates from precomputed Gi0 (lookup by last index)
    {
      int lsI = sol_s[t], lgI = sol_g[t];
      gi2[tid] = make_float2(g_gi0[(b * 100 + lsI) * 384 + tid],
                             g_gi0[(b * 100 + lgI) * 384 + tid]);
    }
    // layer-0 hidden gemv: gh = h0 @ Whh0 + bh0 (both streams)
    {
      float ghs = bh0s[tid], ghg = ghs;
#pragma unroll 16
      for (int kk = 0; kk < 32; kk++) {
        float4 w = Wp0[kk * 384 + tid];
        float2 a0 = h0s[4 * kk], a1 = h0s[4 * kk + 1];
        float2 a2 = h0s[4 * kk + 2], a3 = h0s[4 * kk + 3];
        ghs = fmaf(a3.x, w.w, fmaf(a2.x, w.z, fmaf(a1.x, w.y, fmaf(a0.x, w.x, ghs))));
        ghg = fmaf(a3.y, w.w, fmaf(a2.y, w.z, fmaf(a1.y, w.y, fmaf(a0.y, w.x, ghg))));
      }
      gh2[tid] = make_float2(ghs, ghg);
    }
    __syncthreads();
    if (tid < 128) {
      float2 ir = gi2[tid], iz = gi2[tid + 128], in_ = gi2[tid + 256];
      float2 hr = gh2[tid], hz = gh2[tid + 128], hn  = gh2[tid + 256];
      float2 hp = h0s[tid];
      float r0 = sigm(ir.x + hr.x), z0 = sigm(iz.x + hz.x), n0 = tanhf(in_.x + r0 * hn.x);
      float r1 = sigm(ir.y + hr.y), z1 = sigm(iz.y + hz.y), n1 = tanhf(in_.y + r1 * hn.y);
      h0s[tid] = make_float2((1.f - z0) * n0 + z0 * hp.x, (1.f - z1) * n1 + z1 * hp.y);
    }
    __syncthreads();
    // layer-1 gemv: gi = h0 @ Wih1 + bi1 ; gh = h1 @ Whh1 + bh1
    {
      float gis = bi1s[tid], gig = gis, ghs = bh1s[tid], ghg = ghs;
#pragma unroll 8
      for (int kk = 0; kk < 32; kk++) {
        float4 wi = Wp1[kk * 384 + tid];
        float4 wh = Wp2[kk * 384 + tid];
        float2 a0 = h0s[4 * kk], a1 = h0s[4 * kk + 1];
        float2 a2 = h0s[4 * kk + 2], a3 = h0s[4 * kk + 3];
        float2 c0 = h1s[4 * kk], c1 = h1s[4 * kk + 1];
        float2 c2 = h1s[4 * kk + 2], c3 = h1s[4 * kk + 3];
        gis = fmaf(a3.x, wi.w, fmaf(a2.x, wi.z, fmaf(a1.x, wi.y, fmaf(a0.x, wi.x, gis))));
        gig = fmaf(a3.y, wi.w, fmaf(a2.y, wi.z, fmaf(a1.y, wi.y, fmaf(a0.y, wi.x, gig))));
        ghs = fmaf(c3.x, wh.w, fmaf(c2.x, wh.z, fmaf(c1.x, wh.y, fmaf(c0.x, wh.x, ghs))));
        ghg = fmaf(c3.y, wh.w, fmaf(c2.y, wh.z, fmaf(c1.y, wh.y, fmaf(c0.y, wh.x, ghg))));
      }
      gi2[tid] = make_float2(gis, gig); gh2[tid] = make_float2(ghs, ghg);
    }
    __syncthreads();
    if (tid < 128) {
      float2 ir = gi2[tid], iz = gi2[tid + 128], in_ = gi2[tid + 256];
      float2 hr = gh2[tid], hz = gh2[tid + 128], hn  = gh2[tid + 256];
      float2 hp = h1s[tid];
      float r0 = sigm(ir.x + hr.x), z0 = sigm(iz.x + hz.x), n0 = tanhf(in_.x + r0 * hn.x);
      float r1 = sigm(ir.y + hr.y), z1 = sigm(iz.y + hz.y), n1 = tanhf(in_.y + r1 * hn.y);
      h1s[tid] = make_float2((1.f - z0) * n0 + z0 * hp.x, (1.f - z1) * n1 + z1 * hp.y);
    }
    __syncthreads();
    // logits_i = h1 . Y_i  (12 warps over 100 nodes)
    for (int i = wrp; i < 100; i += 12) {
      float ssx = 0.f, ggx = 0.f;
#pragma unroll
      for (int r = 0; r < 4; r++) {
        int k = lane + 32 * r;
        float2 h = h1s[k]; float yv = Y_s[i * 128 + k];
        ssx = fmaf(h.x, yv, ssx); ggx = fmaf(h.y, yv, ggx);
      }
#pragma unroll
      for (int o = 16; o > 0; o >>= 1) {
        ssx += __shfl_xor_sync(0xffffffffu, ssx, o);
        ggx += __shfl_xor_sync(0xffffffffu, ggx, o);
      }
      if (lane == 0) {
        float lsv = ssx * scale;
        ls[i] = lsv;
        ys[i] = lsv + gums[i];
        lg[i] = ggx * scale;
      }
    }
    __syncthreads();
    // reductions
    if (wrp == 0) {
      float bv = -3.4e38f; int bi_ = 0;
#pragma unroll
      for (int r = 0; r < 4; r++) { int i = lane + 32 * r; if (i < 100) { float v = ys[i]; if (v > bv) { bv = v; bi_ = i; } } }
#pragma unroll
      for (int o = 16; o > 0; o >>= 1) {
        float ov = __shfl_xor_sync(0xffffffffu, bv, o);
        int   oi = __shfl_xor_sync(0xffffffffu, bi_, o);
        if (ov > bv || (ov == bv && oi < bi_)) { bv = ov; bi_ = oi; }
      }
      if (lane == 0) sh_i[0] = bi_;
    } else if (wrp == 1) {
      float bv = -3.4e38f; int bi_ = 0;
#pragma unroll
      for (int r = 0; r < 4; r++) { int i = lane + 32 * r; if (i < 100) { float v = lg[i]; if (v > bv) { bv = v; bi_ = i; } } }
#pragma unroll
      for (int o = 16; o > 0; o >>= 1) {
        float ov = __shfl_xor_sync(0xffffffffu, bv, o);
        int   oi = __shfl_xor_sync(0xffffffffu, bi_, o);
        if (ov > bv || (ov == bv && oi < bi_)) { bv = ov; bi_ = oi; }
      }
      if (lane == 0) sh_i[1] = bi_;
    } else if (wrp == 2) {
      float m = -3.4e38f;
#pragma unroll
      for (int r = 0; r < 4; r++) { int i = lane + 32 * r; if (i < 100) m = fmaxf(m, ls[i]); }
#pragma unroll
      for (int o = 16; o > 0; o >>= 1) m = fmaxf(m, __shfl_xor_sync(0xffffffffu, m, o));
      if (lane == 0) red[0] = m;
    }
    __syncthreads();
    if (wrp == 2) {
      float m = red[0], s = 0.f;
#pragma unroll
      for (int r = 0; r < 4; r++) { int i = lane + 32 * r; if (i < 100) s += expf(ls[i] - m); }
#pragma unroll
      for (int o = 16; o > 0; o >>= 1) s += __shfl_xor_sync(0xffffffffu, s, o);
      if (lane == 0) {
        int is_ = sh_i[0], ig_ = sh_i[1];
        out[OFF_LOGP + b * 99 + t] = ls[is_] - m - logf(s);
        sol_s[t + 1] = is_; sol_g[t + 1] = ig_;
      }
    }
    __syncthreads();
  }
  // epilogue: distances + greedy solution export
  if (tid == 0) { red[2] = 0.f; red[3] = 0.f; }
  __syncthreads();
  if (tid < 99) {
    atomicAdd(&red[2], dis[b * 10000 + sol_s[tid] * 100 + sol_s[tid + 1]]);
    atomicAdd(&red[3], dis[b * 10000 + sol_g[tid] * 100 + sol_g[tid + 1]]);
  }
  for (int i = tid; i < 100; i += 384) g_solg[b * 100 + i] = sol_g[i];
  __syncthreads();
  if (tid == 0) { out[OFF_SD + b] = red[2]; out[OFF_GD + b] = red[3]; }
}

// ---------------- predict_matrix fused, warp per (b,i,j) ----------------
__global__ void k_pred(const float* __restrict__ dis, const float* __restrict__ We,
                       const float* __restrict__ be, const float* __restrict__ Wc,
                       const float* __restrict__ bc, float* __restrict__ out) {
  int lane = threadIdx.x & 31;
  int gw = (blockIdx.x * blockDim.x + threadIdx.x) >> 5;
  int nw = (gridDim.x * blockDim.x) >> 5;
  float we[4], bee[4], wc0[4], wc1[4];
#pragma unroll
  for (int u = 0; u < 4; u++) {
    int k = lane * 4 + u;
    we[u] = We[k]; bee[u] = be[k]; wc0[u] = Wc[k * 2]; wc1[u] = Wc[k * 2 + 1];
  }
  float bc0 = bc[0], bc1 = bc[1];
  for (int p = gw; p < 640000; p += nw) {
    float d = dis[p];
    float y0 = 0.f, y1 = 0.f;
#pragma unroll
    for (int u = 0; u < 4; u++) {
      float e = fmaxf(fmaf(d, we[u], bee[u]), 0.f);
      y0 = fmaf(e, wc0[u], y0); y1 = fmaf(e, wc1[u], y1);
    }
#pragma unroll
    for (int o = 16; o > 0; o >>= 1) {
      y0 += __shfl_xor_sync(0xffffffffu, y0, o);
      y1 += __shfl_xor_sync(0xffffffffu, y1, o);
    }
    if (lane == 0) {
      y0 += bc0; y1 += bc1;
      float m = fmaxf(y0, y1);
      float e0 = expf(y0 - m), e1 = expf(y1 - m), s = e0 + e1;
      out[OFF_PRED + p * 2]     = e0 / s;
      out[OFF_PRED + p * 2 + 1] = e1 / s;
    }
  }
}

__global__ void k_gzero(float* __restrict__ out) {
  int idx = blockIdx.x * blockDim.x + threadIdx.x;
  if (idx < 640000) out[OFF_GSOL + idx] = 0.f;
}

__global__ void k_gset(float* __restrict__ out) {
  int b = blockIdx.x, t = threadIdx.x;
  if (t < 99) {
    int u = g_solg[b * 100 + t], v = g_solg[b * 100 + t + 1];
    out[OFF_GSOL + b * 10000 + u * 100 + v] = 1.0f;
  }
}

extern "C" void kernel_launch(void* const* d_in, const int* in_sizes, int n_in,
                              void* d_out, int out_size) {
  const float* node   = (const float*)d_in[0];
  const float* demand = (const float*)d_in[1];
  const float* dis    = (const float*)d_in[2];
  const float* Wn0    = (const float*)d_in[3];
  const float* bn0    = (const float*)d_in[4];
  const float* Ws     = (const float*)d_in[5];
  const float* Wngh   = (const float*)d_in[6];
  const float* We     = (const float*)d_in[7];
  const float* be     = (const float*)d_in[8];
  const float* Wih    = (const float*)d_in[9];
  const float* Whh    = (const float*)d_in[10];
  const float* bih    = (const float*)d_in[11];
  const float* bhh    = (const float*)d_in[12];
  const float* Wq     = (const float*)d_in[13];
  const float* Wc     = (const float*)d_in[14];
  const float* bc     = (const float*)d_in[15];
  float* out = (float*)d_out;

  cudaFuncSetAttribute(k_aggr,   cudaFuncAttributeMaxDynamicSharedMemorySize, AGGR2_SMEM);
  cudaFuncSetAttribute(k_y,      cudaFuncAttributeMaxDynamicSharedMemorySize, Y_SMEM);
  cudaFuncSetAttribute(k_decode, cudaFuncAttributeMaxDynamicSharedMemorySize, DEC_FLOATS * 4);

  k_h0<<<3200, 256>>>(node, demand, Wn0, bn0);
  k_softA<<<1600, 128>>>(dis);
  int src = 0;
  for (int l = 0; l < 3; l++) {
    k_gemm2<<<800, 128>>>(src, Ws + l * 16384, Wngh + l * 16384);
    int dst = 1 - src;
    k_aggr<<<dim3(64, 4), 256, AGGR2_SMEM>>>(dst);
    src = dst;
  }
  // final h in g_buf1
  k_gi0<<<800, 384>>>(Wih, bih);
  k_y<<<800, 128, Y_SMEM>>>(Wq);
  k_pack<<<576, 256>>>(Wih, Whh);
  k_gumbel<<<99, 256>>>();
  k_decode<<<64, 384, DEC_FLOATS * 4>>>(dis, bih, bhh, out);
  k_pred<<<1280, 256>>>(dis, We, be, Wc, bc, out);
  k_gzero<<<2500, 256>>>(out);
  k_gset<<<64, 128>>>(out);
}

// round 6
// speedup vs baseline: 3.0238x; 1.0789x over previous
#include <cuda_runtime.h>
#include <stdint.h>

#define OFF_LOGP 0
#define OFF_SD   6336
#define OFF_GD   6400
#define OFF_PRED 6464
#define OFF_GSOL 1286464

__device__ float g_buf0[819200];
__device__ float g_buf1[819200];
__device__ float g_hWs[819200];
__device__ float g_hN[819200];
__device__ float g_A[640000];
__device__ float g_gum[633600];    // 99 * 6400
__device__ int   g_solg[6400];
__device__ float g_gi0[2457600];   // [64][100][384] precomputed x@Wih0+bih0
__device__ float g_y[819200];      // [64][100][128] precomputed (x@Wq^T)*scale
__device__ float4 g_wpack4[36864]; // packed Wh0,Wi1,Wh1: [(m*32+kk)*384+o] -> k=4kk+u

// ---------------- threefry2x32 (exact JAX) ----------------
__device__ __forceinline__ void tf2x32(uint32_t k0, uint32_t k1,
                                       uint32_t c0, uint32_t c1,
                                       uint32_t& o0, uint32_t& o1) {
  uint32_t ks0 = k0, ks1 = k1, ks2 = k0 ^ k1 ^ 0x1BD11BDAu;
  uint32_t x0 = c0 + ks0, x1 = c1 + ks1;
#define TF_RND(R) { x0 += x1; x1 = __funnelshift_l(x1, x1, (R)); x1 ^= x0; }
  TF_RND(13) TF_RND(15) TF_RND(26) TF_RND(6)   x0 += ks1; x1 += ks2 + 1u;
  TF_RND(17) TF_RND(29) TF_RND(16) TF_RND(24)  x0 += ks2; x1 += ks0 + 2u;
  TF_RND(13) TF_RND(15) TF_RND(26) TF_RND(6)   x0 += ks0; x1 += ks1 + 3u;
  TF_RND(17) TF_RND(29) TF_RND(16) TF_RND(24)  x0 += ks1; x1 += ks2 + 4u;
  TF_RND(13) TF_RND(15) TF_RND(26) TF_RND(6)   x0 += ks2; x1 += ks0 + 5u;
#undef TF_RND
  o0 = x0; o1 = x1;
}

// ---------------- h0 = relu([node,demand] @ Wn0 + bn0) ----------------
__global__ void k_h0(const float* __restrict__ node, const float* __restrict__ demand,
                     const float* __restrict__ Wn0, const float* __restrict__ bn0) {
  int idx = blockIdx.x * blockDim.x + threadIdx.x;
  if (idx >= 819200) return;
  int row = idx >> 7, j = idx & 127;
  float v = bn0[j];
  v = fmaf(node[row * 2],     Wn0[j],       v);
  v = fmaf(node[row * 2 + 1], Wn0[128 + j], v);
  v = fmaf(demand[row],       Wn0[256 + j], v);
  g_buf0[idx] = fmaxf(v, 0.f);
}

// ---------------- A = softmax(-dis, -1), warp per row ----------------
__global__ void k_softA(const float* __restrict__ dis) {
  int row  = blockIdx.x * 4 + (threadIdx.x >> 5);
  int lane = threadIdx.x & 31;
  if (row >= 6400) return;
  const float* d = dis + row * 100;
  float v0 = -d[lane], v1 = -d[lane + 32], v2 = -d[lane + 64];
  float v3 = (lane + 96 < 100) ? -d[lane + 96] : -3.4e38f;
  float m = fmaxf(fmaxf(v0, v1), fmaxf(v2, v3));
#pragma unroll
  for (int o = 16; o > 0; o >>= 1) m = fmaxf(m, __shfl_xor_sync(0xffffffffu, m, o));
  float e0 = expf(v0 - m), e1 = expf(v1 - m), e2 = expf(v2 - m);
  float e3 = (lane + 96 < 100) ? expf(v3 - m) : 0.f;
  float s = e0 + e1 + e2 + e3;
#pragma unroll
  for (int o = 16; o > 0; o >>= 1) s += __shfl_xor_sync(0xffffffffu, s, o);
  float* Ar = g_A + row * 100;
  Ar[lane] = e0 / s; Ar[lane + 32] = e1 / s; Ar[lane + 64] = e2 / s;
  if (lane + 96 < 100) Ar[lane + 96] = e3 / s;
}

// ---------------- hWs = h@Ws[l], hN = h@Wngh[l]; 16 rows per block ----------------
__global__ void k_gemm2(int src, const float* __restrict__ W1, const float* __restrict__ W2) {
  const float* h = src ? g_buf1 : g_buf0;
  __shared__ float acts[16][128];
  int j = threadIdx.x;
  int row0 = blockIdx.x * 16;
  for (int i = j; i < 2048; i += 128) acts[i >> 7][i & 127] = h[row0 * 128 + i];
  __syncthreads();
  float aS[16], aN[16];
#pragma unroll
  for (int r = 0; r < 16; r++) { aS[r] = 0.f; aN[r] = 0.f; }
#pragma unroll 4
  for (int k = 0; k < 128; k++) {
    float ws = __ldg(W1 + k * 128 + j);
    float wn = __ldg(W2 + k * 128 + j);
#pragma unroll
    for (int r = 0; r < 16; r++) {
      float a = acts[r][k];
      aS[r] = fmaf(a, ws, aS[r]);
      aN[r] = fmaf(a, wn, aN[r]);
    }
  }
#pragma unroll
  for (int r = 0; r < 16; r++) {
    g_hWs[(row0 + r) * 128 + j] = aS[r];
    g_hN [(row0 + r) * 128 + j] = aN[r];
  }
}

// ---------------- h_next = relu(hWs + A @ hN); grid (64,4), 512 threads ----------------
#define AGGR2_SMEM ((12800 + 2500) * 4)
__global__ void k_aggr(int dst) {
  extern __shared__ float sm[];
  float* hN_s = sm;            // [100][128]
  float* A_s  = sm + 12800;    // [25][100]
  int b = blockIdx.x, r0 = blockIdx.y * 25, tid = threadIdx.x;
  for (int i = tid; i < 12800; i += 512) hN_s[i] = g_hN[b * 12800 + i];
  for (int i = tid; i < 2500; i += 512)  A_s[i]  = g_A [b * 10000 + r0 * 100 + i];
  __syncthreads();
  float* ho = dst ? g_buf1 : g_buf0;
  int j = tid & 127, g = tid >> 7;   // 4 groups of 128
  for (int il = g; il < 25; il += 8) {
    int i2 = il + 4;
    bool two = i2 < 25;
    float a0 = 0.f, a1 = 0.f, c0 = 0.f, c1 = 0.f;
#pragma unroll 10
    for (int p = 0; p < 100; p += 2) {
      float h0v = hN_s[p * 128 + j], h1v = hN_s[(p + 1) * 128 + j];
      a0 = fmaf(A_s[il * 100 + p],     h0v, a0);
      a1 = fmaf(A_s[il * 100 + p + 1], h1v, a1);
      if (two) {
        c0 = fmaf(A_s[i2 * 100 + p],     h0v, c0);
        c1 = fmaf(A_s[i2 * 100 + p + 1], h1v, c1);
      }
    }
    int row = b * 100 + r0 + il;
    ho[row * 128 + j] = fmaxf(g_hWs[row * 128 + j] + a0 + a1, 0.f);
    if (two)
      ho[(row + 4) * 128 + j] = fmaxf(g_hWs[(row + 4) * 128 + j] + c0 + c1, 0.f);
  }
}

// ---------------- precompute Gi0 = x @ Wih0 + bih0 ; 8 rows/block, 384 threads ----------------
__global__ void k_gi0(const float* __restrict__ Wih, const float* __restrict__ bih) {
  __shared__ float acts[8][128];
  int o = threadIdx.x;
  int row0 = blockIdx.x * 8;
  for (int i = o; i < 1024; i += 384) acts[i >> 7][i & 127] = g_buf1[row0 * 128 + i];
  __syncthreads();
  float a[8];
  float bv = bih[o];
#pragma unroll
  for (int r = 0; r < 8; r++) a[r] = bv;
#pragma unroll 8
  for (int k = 0; k < 128; k++) {
    float w = __ldg(Wih + k * 384 + o);
#pragma unroll
    for (int r = 0; r < 8; r++) a[r] = fmaf(acts[r][k], w, a[r]);
  }
#pragma unroll
  for (int r = 0; r < 8; r++) g_gi0[(row0 + r) * 384 + o] = a[r];
}

// ---------------- precompute Y[b,i,k] = scale * sum_j Wq[k,j]*x[b,i,j] ----------------
#define Y_SMEM ((129 * 128 + 1024) * 4)
__global__ void k_y(const float* __restrict__ Wq) {
  extern __shared__ float sm[];
  float* wq_t = sm;            // [j][k] padded 129
  float* acts = sm + 16512;    // [8][128]
  int tid = threadIdx.x;
  int row0 = blockIdx.x * 8;
  for (int i = tid; i < 16384; i += 128) {
    int k = i >> 7, j = i & 127;
    wq_t[j * 129 + k] = Wq[i];
  }
  for (int i = tid; i < 1024; i += 128) acts[i] = g_buf1[row0 * 128 + i];
  __syncthreads();
  const float scale = (float)(1.0 / (double)sqrtf(128.0f));
  int k = tid;
  float a[8];
#pragma unroll
  for (int r = 0; r < 8; r++) a[r] = 0.f;
#pragma unroll 4
  for (int j = 0; j < 128; j++) {
    float w = wq_t[j * 129 + k];
#pragma unroll
    for (int r = 0; r < 8; r++) a[r] = fmaf(acts[r * 128 + j], w, a[r]);
  }
#pragma unroll
  for (int r = 0; r < 8; r++) g_y[(row0 + r) * 128 + k] = a[r] * scale;
}

// ---------------- pack Wh0, Wi1, Wh1 into float4-friendly layout ----------------
__global__ void k_pack(const float* __restrict__ Wih, const float* __restrict__ Whh) {
  int idx = blockIdx.x * blockDim.x + threadIdx.x;
  if (idx >= 147456) return;
  int m = idx / 49152, r = idx % 49152;
  int t4 = r >> 2, u = r & 3;
  int o = t4 % 384, kk = t4 / 384;
  int k = kk * 4 + u;
  const float* src = (m == 0) ? Whh : (m == 1 ? (Wih + 49152) : (Whh + 49152));
  ((float*)g_wpack4)[idx] = src[k * 384 + o];
}

// ---------------- gumbel precompute: block t handles step t ----------------
__global__ void k_gumbel() {
  int t = blockIdx.x;
  __shared__ uint32_t sk0, sk1;
  if (threadIdx.x == 0) {
    uint32_t k0 = 0u, k1 = 42u, a, b;
    tf2x32(k0, k1, 0u, 0u, a, b); k0 = a; k1 = b;
    for (int i = 0; i < t; i++) { tf2x32(k0, k1, 0u, 0u, a, b); k0 = a; k1 = b; }
    tf2x32(k0, k1, 0u, 1u, a, b); sk0 = a; sk1 = b;
  }
  __syncthreads();
  const float TINY = 1.17549435e-38f;
  uint32_t s0 = sk0, s1 = sk1;
  for (int i = threadIdx.x; i < 6400; i += blockDim.x) {
    uint32_t o0, o1;
    tf2x32(s0, s1, 0u, (uint32_t)i, o0, o1);
    uint32_t bits = o0 ^ o1;
    float f = __uint_as_float((bits >> 9) | 0x3f800000u) - 1.0f;
    float u = fmaxf(TINY, f + TINY);
    g_gum[t * 6400 + i] = -logf(-logf(u));
  }
}

__device__ __forceinline__ float sigm(float x) { return 1.f / (1.f + expf(-x)); }

// ---------------- fused dual-stream decoder ----------------
#define DEC_FLOATS 16708
__global__ void __launch_bounds__(384, 1) k_decode(
    const float* __restrict__ dis, const float* __restrict__ bih,
    const float* __restrict__ bhh, float* __restrict__ out) {
  extern __shared__ float sm[];
  const int tid = threadIdx.x, b = blockIdx.x;
  const int lane = tid & 31, wrp = tid >> 5;

  float*  Y_s  = sm;                      // [100][129]
  float*  bh0s = sm + 12900;              // [384]
  float*  bi1s = sm + 13284;
  float*  bh1s = sm + 13668;
  float2* gi2  = (float2*)(sm + 14052);   // [384]
  float2* gh2  = (float2*)(sm + 14820);   // [384]
  float2* h0s  = (float2*)(sm + 15588);   // [128]
  float2* h1s  = (float2*)(sm + 15844);   // [128]
  float*  gums = sm + 16100;              // [100]
  float*  ls   = sm + 16200;
  float*  lg   = sm + 16300;
  float*  ys   = sm + 16400;
  float*  red  = sm + 16500;              // [4]
  int*    sol_s = (int*)(sm + 16504);     // [100]
  int*    sol_g = (int*)(sm + 16604);     // [100]
  int*    sh_i  = (int*)(sm + 16704);     // [2]

  for (int i = tid; i < 12800; i += 384) {
    int r = i >> 7, c = i & 127;
    Y_s[r * 129 + c] = g_y[b * 12800 + i];
  }
  bh0s[tid] = bhh[tid];
  bi1s[tid] = bih[384 + tid];
  bh1s[tid] = bhh[384 + tid];
  if (tid < 128) { h0s[tid] = make_float2(0.f, 0.f); h1s[tid] = make_float2(0.f, 0.f); }
  if (tid == 0)  { sol_s[0] = 0; sol_g[0] = 0; }
  __syncthreads();

  const float4* Wp0 = g_wpack4;            // Wh0
  const float4* Wp1 = g_wpack4 + 12288;    // Wi1
  const float4* Wp2 = g_wpack4 + 24576;    // Wh1

  for (int t = 0; t < 99; t++) {
    // gumbel prefetch (warp 11)
    if (wrp == 11)
      for (int i = lane; i < 100; i += 32) gums[i] = g_gum[t * 6400 + b * 100 + i];
    // Gi0 rows for both streams -> registers (LDGs issue early, consumed late)
    int lsI = sol_s[t], lgI = sol_g[t];
    float gi_s = __ldg(g_gi0 + (b * 100 + lsI) * 384 + tid);
    float gi_g = __ldg(g_gi0 + (b * 100 + lgI) * 384 + tid);
    // layer-0 hidden gemv: gh = h0 @ Whh0 + bh0 (both streams)
    float ghs = bh0s[tid], ghg = ghs;
#pragma unroll 16
    for (int kk = 0; kk < 32; kk++) {
      float4 w = Wp0[kk * 384 + tid];
      float2 a0 = h0s[4 * kk], a1 = h0s[4 * kk + 1];
      float2 a2 = h0s[4 * kk + 2], a3 = h0s[4 * kk + 3];
      ghs = fmaf(a3.x, w.w, fmaf(a2.x, w.z, fmaf(a1.x, w.y, fmaf(a0.x, w.x, ghs))));
      ghg = fmaf(a3.y, w.w, fmaf(a2.y, w.z, fmaf(a1.y, w.y, fmaf(a0.y, w.x, ghg))));
    }
    gi2[tid] = make_float2(gi_s, gi_g);
    gh2[tid] = make_float2(ghs, ghg);
    __syncthreads();
    if (tid < 128) {
      float2 ir = gi2[tid], iz = gi2[tid + 128], in_ = gi2[tid + 256];
      float2 hr = gh2[tid], hz = gh2[tid + 128], hn  = gh2[tid + 256];
      float2 hp = h0s[tid];
      float r0 = sigm(ir.x + hr.x), z0 = sigm(iz.x + hz.x), n0 = tanhf(in_.x + r0 * hn.x);
      float r1 = sigm(ir.y + hr.y), z1 = sigm(iz.y + hz.y), n1 = tanhf(in_.y + r1 * hn.y);
      h0s[tid] = make_float2((1.f - z0) * n0 + z0 * hp.x, (1.f - z1) * n1 + z1 * hp.y);
    }
    __syncthreads();
    // layer-1 gemv: gi = h0 @ Wih1 + bi1 ; gh = h1 @ Whh1 + bh1
    {
      float gis = bi1s[tid], gig = gis, ghs1 = bh1s[tid], ghg1 = ghs1;
#pragma unroll 8
      for (int kk = 0; kk < 32; kk++) {
        float4 wi = Wp1[kk * 384 + tid];
        float4 wh = Wp2[kk * 384 + tid];
        float2 a0 = h0s[4 * kk], a1 = h0s[4 * kk + 1];
        float2 a2 = h0s[4 * kk + 2], a3 = h0s[4 * kk + 3];
        float2 c0 = h1s[4 * kk], c1 = h1s[4 * kk + 1];
        float2 c2 = h1s[4 * kk + 2], c3 = h1s[4 * kk + 3];
        gis  = fmaf(a3.x, wi.w, fmaf(a2.x, wi.z, fmaf(a1.x, wi.y, fmaf(a0.x, wi.x, gis))));
        gig  = fmaf(a3.y, wi.w, fmaf(a2.y, wi.z, fmaf(a1.y, wi.y, fmaf(a0.y, wi.x, gig))));
        ghs1 = fmaf(c3.x, wh.w, fmaf(c2.x, wh.z, fmaf(c1.x, wh.y, fmaf(c0.x, wh.x, ghs1))));
        ghg1 = fmaf(c3.y, wh.w, fmaf(c2.y, wh.z, fmaf(c1.y, wh.y, fmaf(c0.y, wh.x, ghg1))));
      }
      gi2[tid] = make_float2(gis, gig); gh2[tid] = make_float2(ghs1, ghg1);
    }
    __syncthreads();
    if (tid < 128) {
      float2 ir = gi2[tid], iz = gi2[tid + 128], in_ = gi2[tid + 256];
      float2 hr = gh2[tid], hz = gh2[tid + 128], hn  = gh2[tid + 256];
      float2 hp = h1s[tid];
      float r0 = sigm(ir.x + hr.x), z0 = sigm(iz.x + hz.x), n0 = tanhf(in_.x + r0 * hn.x);
      float r1 = sigm(ir.y + hr.y), z1 = sigm(iz.y + hz.y), n1 = tanhf(in_.y + r1 * hn.y);
      h1s[tid] = make_float2((1.f - z0) * n0 + z0 * hp.x, (1.f - z1) * n1 + z1 * hp.y);
    }
    __syncthreads();
    // logits: thread-per-row, no shuffles (Y padded 129, h1s broadcast)
    if (tid < 100) {
      const float* yr = Y_s + tid * 129;
      float ss0 = 0.f, ss1 = 0.f, gg0 = 0.f, gg1 = 0.f;
#pragma unroll 8
      for (int k = 0; k < 128; k += 2) {
        float2 ha = h1s[k], hb = h1s[k + 1];
        float ya = yr[k], yb = yr[k + 1];
        ss0 = fmaf(ha.x, ya, ss0); gg0 = fmaf(ha.y, ya, gg0);
        ss1 = fmaf(hb.x, yb, ss1); gg1 = fmaf(hb.y, yb, gg1);
      }
      float lsv = ss0 + ss1, lgv = gg0 + gg1;
      ls[tid] = lsv;
      ys[tid] = lsv + gums[tid];
      lg[tid] = lgv;
    }
    __syncthreads();
    // single-phase reductions: warp0 argmax(ys), warp1 argmax(lg), warp2 sum exp(ls)
    if (wrp == 0) {
      float bv = -3.4e38f; int bi_ = 0;
#pragma unroll
      for (int r = 0; r < 4; r++) { int i = lane + 32 * r; if (i < 100) { float v = ys[i]; if (v > bv) { bv = v; bi_ = i; } } }
#pragma unroll
      for (int o = 16; o > 0; o >>= 1) {
        float ov = __shfl_xor_sync(0xffffffffu, bv, o);
        int   oi = __shfl_xor_sync(0xffffffffu, bi_, o);
        if (ov > bv || (ov == bv && oi < bi_)) { bv = ov; bi_ = oi; }
      }
      if (lane == 0) sh_i[0] = bi_;
    } else if (wrp == 1) {
      float bv = -3.4e38f; int bi_ = 0;
#pragma unroll
      for (int r = 0; r < 4; r++) { int i = lane + 32 * r; if (i < 100) { float v = lg[i]; if (v > bv) { bv = v; bi_ = i; } } }
#pragma unroll
      for (int o = 16; o > 0; o >>= 1) {
        float ov = __shfl_xor_sync(0xffffffffu, bv, o);
        int   oi = __shfl_xor_sync(0xffffffffu, bi_, o);
        if (ov > bv || (ov == bv && oi < bi_)) { bv = ov; bi_ = oi; }
      }
      if (lane == 0) sh_i[1] = bi_;
    } else if (wrp == 2) {
      float s = 0.f;
#pragma unroll
      for (int r = 0; r < 4; r++) { int i = lane + 32 * r; if (i < 100) s += expf(ls[i]); }
#pragma unroll
      for (int o = 16; o > 0; o >>= 1) s += __shfl_xor_sync(0xffffffffu, s, o);
      if (lane == 0) red[1] = s;
    }
    __syncthreads();
    if (tid == 0) {
      int is_ = sh_i[0], ig_ = sh_i[1];
      out[OFF_LOGP + b * 99 + t] = ls[is_] - logf(red[1]);
      sol_s[t + 1] = is_; sol_g[t + 1] = ig_;
    }
    __syncthreads();
  }
  // epilogue
  if (tid == 0) { red[2] = 0.f; red[3] = 0.f; }
  __syncthreads();
  if (tid < 99) {
    atomicAdd(&red[2], dis[b * 10000 + sol_s[tid] * 100 + sol_s[tid + 1]]);
    atomicAdd(&red[3], dis[b * 10000 + sol_g[tid] * 100 + sol_g[tid + 1]]);
  }
  for (int i = tid; i < 100; i += 384) g_solg[b * 100 + i] = sol_g[i];
  __syncthreads();
  if (tid == 0) { out[OFF_SD + b] = red[2]; out[OFF_GD + b] = red[3]; }
}

// ---------------- predict_matrix fused, warp per (b,i,j) ----------------
__global__ void k_pred(const float* __restrict__ dis, const float* __restrict__ We,
                       const float* __restrict__ be, const float* __restrict__ Wc,
                       const float* __restrict__ bc, float* __restrict__ out) {
  int lane = threadIdx.x & 31;
  int gw = (blockIdx.x * blockDim.x + threadIdx.x) >> 5;
  int nw = (gridDim.x * blockDim.x) >> 5;
  float we[4], bee[4], wc0[4], wc1[4];
#pragma unroll
  for (int u = 0; u < 4; u++) {
    int k = lane * 4 + u;
    we[u] = We[k]; bee[u] = be[k]; wc0[u] = Wc[k * 2]; wc1[u] = Wc[k * 2 + 1];
  }
  float bc0 = bc[0], bc1 = bc[1];
  for (int p = gw; p < 640000; p += nw) {
    float d = dis[p];
    float y0 = 0.f, y1 = 0.f;
#pragma unroll
    for (int u = 0; u < 4; u++) {
      float e = fmaxf(fmaf(d, we[u], bee[u]), 0.f);
      y0 = fmaf(e, wc0[u], y0); y1 = fmaf(e, wc1[u], y1);
    }
#pragma unroll
    for (int o = 16; o > 0; o >>= 1) {
      y0 += __shfl_xor_sync(0xffffffffu, y0, o);
      y1 += __shfl_xor_sync(0xffffffffu, y1, o);
    }
    if (lane == 0) {
      y0 += bc0; y1 += bc1;
      float m = fmaxf(y0, y1);
      float e0 = expf(y0 - m), e1 = expf(y1 - m), s = e0 + e1;
      out[OFF_PRED + p * 2]     = e0 / s;
      out[OFF_PRED + p * 2 + 1] = e1 / s;
    }
  }
}

__global__ void k_gzero(float* __restrict__ out) {
  int idx = blockIdx.x * blockDim.x + threadIdx.x;
  if (idx < 640000) out[OFF_GSOL + idx] = 0.f;
}

__global__ void k_gset(float* __restrict__ out) {
  int b = blockIdx.x, t = threadIdx.x;
  if (t < 99) {
    int u = g_solg[b * 100 + t], v = g_solg[b * 100 + t + 1];
    out[OFF_GSOL + b * 10000 + u * 100 + v] = 1.0f;
  }
}

extern "C" void kernel_launch(void* const* d_in, const int* in_sizes, int n_in,
                              void* d_out, int out_size) {
  const float* node   = (const float*)d_in[0];
  const float* demand = (const float*)d_in[1];
  const float* dis    = (const float*)d_in[2];
  const float* Wn0    = (const float*)d_in[3];
  const float* bn0    = (const float*)d_in[4];
  const float* Ws     = (const float*)d_in[5];
  const float* Wngh   = (const float*)d_in[6];
  const float* We     = (const float*)d_in[7];
  const float* be     = (const float*)d_in[8];
  const float* Wih    = (const float*)d_in[9];
  const float* Whh    = (const float*)d_in[10];
  const float* bih    = (const float*)d_in[11];
  const float* bhh    = (const float*)d_in[12];
  const float* Wq     = (const float*)d_in[13];
  const float* Wc     = (const float*)d_in[14];
  const float* bc     = (const float*)d_in[15];
  float* out = (float*)d_out;

  cudaFuncSetAttribute(k_aggr,   cudaFuncAttributeMaxDynamicSharedMemorySize, AGGR2_SMEM);
  cudaFuncSetAttribute(k_y,      cudaFuncAttributeMaxDynamicSharedMemorySize, Y_SMEM);
  cudaFuncSetAttribute(k_decode, cudaFuncAttributeMaxDynamicSharedMemorySize, DEC_FLOATS * 4);

  k_h0<<<3200, 256>>>(node, demand, Wn0, bn0);
  k_softA<<<1600, 128>>>(dis);
  int src = 0;
  for (int l = 0; l < 3; l++) {
    k_gemm2<<<400, 128>>>(src, Ws + l * 16384, Wngh + l * 16384);
    int dst = 1 - src;
    k_aggr<<<dim3(64, 4), 512, AGGR2_SMEM>>>(dst);
    src = dst;
  }
  // final h in g_buf1
  k_gi0<<<800, 384>>>(Wih, bih);
  k_y<<<800, 128, Y_SMEM>>>(Wq);
  k_pack<<<576, 256>>>(Wih, Whh);
  k_gumbel<<<99, 256>>>();
  k_decode<<<64, 384, DEC_FLOATS * 4>>>(dis, bih, bhh, out);
  k_pred<<<1280, 256>>>(dis, We, be, Wc, bc, out);
  k_gzero<<<2500, 256>>>(out);
  k_gset<<<64, 128>>>(out);
}

// round 7
// speedup vs baseline: 3.9206x; 1.2966x over previous
#include <cuda_runtime.h>
#include <stdint.h>

#define OFF_LOGP 0
#define OFF_SD   6336
#define OFF_GD   6400
#define OFF_PRED 6464
#define OFF_GSOL 1286464

__device__ float g_buf0[819200];
__device__ float g_buf1[819200];
__device__ float g_hWs[819200];
__device__ float g_hN[819200];
__device__ float g_A[640000];
__device__ float g_gum[633600];    // 99 * 6400
__device__ int   g_solg[6400];
__device__ float g_gi0[2457600];   // [64][100][384] x@Wih0+bih0
__device__ float g_y[819200];      // [64][100][128] (x@Wq^T)*scale
__device__ float4 g_wpk0[12288];   // Wh0 halves: [q][kk][192]
__device__ float4 g_wpk12[24576];  // [q][m][kk][192], m=0:Wi1 m=1:Wh1

// ---------------- threefry2x32 (exact JAX) ----------------
__device__ __forceinline__ void tf2x32(uint32_t k0, uint32_t k1,
                                       uint32_t c0, uint32_t c1,
                                       uint32_t& o0, uint32_t& o1) {
  uint32_t ks0 = k0, ks1 = k1, ks2 = k0 ^ k1 ^ 0x1BD11BDAu;
  uint32_t x0 = c0 + ks0, x1 = c1 + ks1;
#define TF_RND(R) { x0 += x1; x1 = __funnelshift_l(x1, x1, (R)); x1 ^= x0; }
  TF_RND(13) TF_RND(15) TF_RND(26) TF_RND(6)   x0 += ks1; x1 += ks2 + 1u;
  TF_RND(17) TF_RND(29) TF_RND(16) TF_RND(24)  x0 += ks2; x1 += ks0 + 2u;
  TF_RND(13) TF_RND(15) TF_RND(26) TF_RND(6)   x0 += ks0; x1 += ks1 + 3u;
  TF_RND(17) TF_RND(29) TF_RND(16) TF_RND(24)  x0 += ks1; x1 += ks2 + 4u;
  TF_RND(13) TF_RND(15) TF_RND(26) TF_RND(6)   x0 += ks2; x1 += ks0 + 5u;
#undef TF_RND
  o0 = x0; o1 = x1;
}

// ---------------- cluster / DSMEM helpers ----------------
__device__ __forceinline__ uint32_t smem_u32(const void* p) {
  uint32_t a;
  asm("{ .reg .u64 t; cvta.to.shared.u64 t, %1; cvt.u32.u64 %0, t; }" : "=r"(a) : "l"(p));
  return a;
}
__device__ __forceinline__ uint32_t ctarank() {
  uint32_t r; asm("mov.u32 %0, %%cluster_ctarank;" : "=r"(r)); return r;
}
__device__ __forceinline__ void peer_st_f2(uint32_t laddr, uint32_t peer, float x, float y) {
  uint32_t ra;
  asm("mapa.shared::cluster.u32 %0, %1, %2;" : "=r"(ra) : "r"(laddr), "r"(peer));
  asm volatile("{ .reg .b64 t; mov.b64 t, {%1, %2}; st.shared::cluster.b64 [%0], t; }"
               :: "r"(ra), "f"(x), "f"(y) : "memory");
}
__device__ __forceinline__ void peer_st_f1(uint32_t laddr, uint32_t peer, float x) {
  uint32_t ra;
  asm("mapa.shared::cluster.u32 %0, %1, %2;" : "=r"(ra) : "r"(laddr), "r"(peer));
  asm volatile("st.shared::cluster.b32 [%0], %1;"
               :: "r"(ra), "r"(__float_as_uint(x)) : "memory");
}
#define CSYNC() do { \
  asm volatile("barrier.cluster.arrive.aligned;" ::: "memory"); \
  asm volatile("barrier.cluster.wait.aligned;"  ::: "memory"); } while (0)

// ---------------- h0 = relu([node,demand] @ Wn0 + bn0) ----------------
__global__ void k_h0(const float* __restrict__ node, const float* __restrict__ demand,
                     const float* __restrict__ Wn0, const float* __restrict__ bn0) {
  int idx = blockIdx.x * blockDim.x + threadIdx.x;
  if (idx >= 819200) return;
  int row = idx >> 7, j = idx & 127;
  float v = bn0[j];
  v = fmaf(node[row * 2],     Wn0[j],       v);
  v = fmaf(node[row * 2 + 1], Wn0[128 + j], v);
  v = fmaf(demand[row],       Wn0[256 + j], v);
  g_buf0[idx] = fmaxf(v, 0.f);
}

// ---------------- A = softmax(-dis, -1), warp per row ----------------
__global__ void k_softA(const float* __restrict__ dis) {
  int row  = blockIdx.x * 4 + (threadIdx.x >> 5);
  int lane = threadIdx.x & 31;
  if (row >= 6400) return;
  const float* d = dis + row * 100;
  float v0 = -d[lane], v1 = -d[lane + 32], v2 = -d[lane + 64];
  float v3 = (lane + 96 < 100) ? -d[lane + 96] : -3.4e38f;
  float m = fmaxf(fmaxf(v0, v1), fmaxf(v2, v3));
#pragma unroll
  for (int o = 16; o > 0; o >>= 1) m = fmaxf(m, __shfl_xor_sync(0xffffffffu, m, o));
  float e0 = expf(v0 - m), e1 = expf(v1 - m), e2 = expf(v2 - m);
  float e3 = (lane + 96 < 100) ? expf(v3 - m) : 0.f;
  float s = e0 + e1 + e2 + e3;
#pragma unroll
  for (int o = 16; o > 0; o >>= 1) s += __shfl_xor_sync(0xffffffffu, s, o);
  float* Ar = g_A + row * 100;
  Ar[lane] = e0 / s; Ar[lane + 32] = e1 / s; Ar[lane + 64] = e2 / s;
  if (lane + 96 < 100) Ar[lane + 96] = e3 / s;
}

// ---------------- hWs = h@Ws[l], hN = h@Wngh[l]; 16 rows per block ----------------
__global__ void k_gemm2(int src, const float* __restrict__ W1, const float* __restrict__ W2) {
  const float* h = src ? g_buf1 : g_buf0;
  __shared__ float acts[16][128];
  int j = threadIdx.x;
  int row0 = blockIdx.x * 16;
  for (int i = j; i < 2048; i += 128) acts[i >> 7][i & 127] = h[row0 * 128 + i];
  __syncthreads();
  float aS[16], aN[16];
#pragma unroll
  for (int r = 0; r < 16; r++) { aS[r] = 0.f; aN[r] = 0.f; }
#pragma unroll 4
  for (int k = 0; k < 128; k++) {
    float ws = __ldg(W1 + k * 128 + j);
    float wn = __ldg(W2 + k * 128 + j);
#pragma unroll
    for (int r = 0; r < 16; r++) {
      float a = acts[r][k];
      aS[r] = fmaf(a, ws, aS[r]);
      aN[r] = fmaf(a, wn, aN[r]);
    }
  }
#pragma unroll
  for (int r = 0; r < 16; r++) {
    g_hWs[(row0 + r) * 128 + j] = aS[r];
    g_hN [(row0 + r) * 128 + j] = aN[r];
  }
}

// ---------------- h_next = relu(hWs + A @ hN); grid (64,4), 512 threads ----------------
#define AGGR2_SMEM ((12800 + 2500) * 4)
__global__ void k_aggr(int dst) {
  extern __shared__ float sm[];
  float* hN_s = sm;
  float* A_s  = sm + 12800;
  int b = blockIdx.x, r0 = blockIdx.y * 25, tid = threadIdx.x;
  for (int i = tid; i < 12800; i += 512) hN_s[i] = g_hN[b * 12800 + i];
  for (int i = tid; i < 2500; i += 512)  A_s[i]  = g_A [b * 10000 + r0 * 100 + i];
  __syncthreads();
  float* ho = dst ? g_buf1 : g_buf0;
  int j = tid & 127, g = tid >> 7;
  for (int il = g; il < 25; il += 8) {
    int i2 = il + 4;
    bool two = i2 < 25;
    float a0 = 0.f, a1 = 0.f, c0 = 0.f, c1 = 0.f;
#pragma unroll 10
    for (int p = 0; p < 100; p += 2) {
      float h0v = hN_s[p * 128 + j], h1v = hN_s[(p + 1) * 128 + j];
      a0 = fmaf(A_s[il * 100 + p],     h0v, a0);
      a1 = fmaf(A_s[il * 100 + p + 1], h1v, a1);
      if (two) {
        c0 = fmaf(A_s[i2 * 100 + p],     h0v, c0);
        c1 = fmaf(A_s[i2 * 100 + p + 1], h1v, c1);
      }
    }
    int row = b * 100 + r0 + il;
    ho[row * 128 + j] = fmaxf(g_hWs[row * 128 + j] + a0 + a1, 0.f);
    if (two)
      ho[(row + 4) * 128 + j] = fmaxf(g_hWs[(row + 4) * 128 + j] + c0 + c1, 0.f);
  }
}

// ---------------- precompute Gi0 = x @ Wih0 + bih0 ----------------
__global__ void k_gi0(const float* __restrict__ Wih, const float* __restrict__ bih) {
  __shared__ float acts[8][128];
  int o = threadIdx.x;
  int row0 = blockIdx.x * 8;
  for (int i = o; i < 1024; i += 384) acts[i >> 7][i & 127] = g_buf1[row0 * 128 + i];
  __syncthreads();
  float a[8];
  float bv = bih[o];
#pragma unroll
  for (int r = 0; r < 8; r++) a[r] = bv;
#pragma unroll 8
  for (int k = 0; k < 128; k++) {
    float w = __ldg(Wih + k * 384 + o);
#pragma unroll
    for (int r = 0; r < 8; r++) a[r] = fmaf(acts[r][k], w, a[r]);
  }
#pragma unroll
  for (int r = 0; r < 8; r++) g_gi0[(row0 + r) * 384 + o] = a[r];
}

// ---------------- precompute Y = (x @ Wq^T)*scale ----------------
#define Y_SMEM ((129 * 128 + 1024) * 4)
__global__ void k_y(const float* __restrict__ Wq) {
  extern __shared__ float sm[];
  float* wq_t = sm;
  float* acts = sm + 16512;
  int tid = threadIdx.x;
  int row0 = blockIdx.x * 8;
  for (int i = tid; i < 16384; i += 128) {
    int k = i >> 7, j = i & 127;
    wq_t[j * 129 + k] = Wq[i];
  }
  for (int i = tid; i < 1024; i += 128) acts[i] = g_buf1[row0 * 128 + i];
  __syncthreads();
  const float scale = (float)(1.0 / (double)sqrtf(128.0f));
  int k = tid;
  float a[8];
#pragma unroll
  for (int r = 0; r < 8; r++) a[r] = 0.f;
#pragma unroll 4
  for (int j = 0; j < 128; j++) {
    float w = wq_t[j * 129 + k];
#pragma unroll
    for (int r = 0; r < 8; r++) a[r] = fmaf(acts[r * 128 + j], w, a[r]);
  }
#pragma unroll
  for (int r = 0; r < 8; r++) g_y[(row0 + r) * 128 + k] = a[r] * scale;
}

// ---------------- pack split weights ----------------
// g_wpk0 floats: idx = ((q*32+kk)*192+o)*4+u -> Whh0[(4kk+u)*384 + col(q,o)]
// g_wpk12:       idx = (((q*2+m)*32+kk)*192+o)*4+u -> (m? Whh1 : Wih1)
__global__ void k_pack2(const float* __restrict__ Wih, const float* __restrict__ Whh) {
  int idx = blockIdx.x * blockDim.x + threadIdx.x;
  if (idx >= 147456) return;
  if (idx < 49152) {
    int f4 = idx >> 2, u = idx & 3;
    int q = f4 / 6144, r4 = f4 % 6144;
    int kk = r4 / 192, o = r4 % 192;
    int col = (o >> 6) * 128 + (q << 6) + (o & 63);
    ((float*)g_wpk0)[idx] = Whh[(4 * kk + u) * 384 + col];
  } else {
    int i2 = idx - 49152;
    int f4 = i2 >> 2, u = i2 & 3;
    int unit = f4 / 6144, r4 = f4 % 6144;
    int q = unit >> 1, m = unit & 1;
    int kk = r4 / 192, o = r4 % 192;
    int col = (o >> 6) * 128 + (q << 6) + (o & 63);
    const float* src = m ? (Whh + 49152) : (Wih + 49152);
    ((float*)g_wpk12)[i2] = src[(4 * kk + u) * 384 + col];
  }
}

// ---------------- gumbel precompute ----------------
__global__ void k_gumbel() {
  int t = blockIdx.x;
  __shared__ uint32_t sk0, sk1;
  if (threadIdx.x == 0) {
    uint32_t k0 = 0u, k1 = 42u, a, b;
    tf2x32(k0, k1, 0u, 0u, a, b); k0 = a; k1 = b;
    for (int i = 0; i < t; i++) { tf2x32(k0, k1, 0u, 0u, a, b); k0 = a; k1 = b; }
    tf2x32(k0, k1, 0u, 1u, a, b); sk0 = a; sk1 = b;
  }
  __syncthreads();
  const float TINY = 1.17549435e-38f;
  uint32_t s0 = sk0, s1 = sk1;
  for (int i = threadIdx.x; i < 6400; i += blockDim.x) {
    uint32_t o0, o1;
    tf2x32(s0, s1, 0u, (uint32_t)i, o0, o1);
    uint32_t bits = o0 ^ o1;
    float f = __uint_as_float((bits >> 9) | 0x3f800000u) - 1.0f;
    float u = fmaxf(TINY, f + TINY);
    g_gum[t * 6400 + i] = -logf(-logf(u));
  }
}

__device__ __forceinline__ float sigm(float x) { return 1.f / (1.f + expf(-x)); }

// ---------------- cluster-of-2 dual-stream decoder ----------------
// smem layout (floats):
//   0      wh0s  float4[6144]          (24576)
//   24576  Y_s   [50*129 + pad]        (6452)
//   31028  h0b   float4[2][64]         (512)
//   31540  h1b   float4[2][64]         (512)
//   32052  gi2   float2[192]           (384)
//   32436  gh2   float2[192]           (384)
//   32820  ls[50] 32870 lg[50] 32920 ys[50]
//   32970  part[16]
//   32986  solS[100](int) 33086 solG[100](int) 33186 red[4]
#define DEC2_FLOATS 33190
__global__ void __cluster_dims__(2, 1, 1) __launch_bounds__(192, 1) k_decode(
    const float* __restrict__ dis, const float* __restrict__ bih,
    const float* __restrict__ bhh, float* __restrict__ out) {
  extern __shared__ float sm[];
  const int tid = threadIdx.x;
  const int b = blockIdx.x >> 1;
  const uint32_t rank = ctarank();
  const uint32_t peer = rank ^ 1u;
  const int lane = tid & 31, wrp = tid >> 5;
  const int col = ((tid >> 6) << 7) + ((int)rank << 6) + (tid & 63);

  float4* wh0s = (float4*)sm;
  float*  Y_s  = sm + 24576;
  float4* h0b  = (float4*)(sm + 31028);
  float4* h1b  = (float4*)(sm + 31540);
  float2* gi2  = (float2*)(sm + 32052);
  float2* gh2  = (float2*)(sm + 32436);
  float*  ls   = sm + 32820;
  float*  lg   = sm + 32870;
  float*  ysA  = sm + 32920;
  float*  part = sm + 32970;
  int*    solS = (int*)(sm + 32986);
  int*    solG = (int*)(sm + 33086);
  float*  red  = sm + 33186;

  const uint32_t sbase = smem_u32(sm);

  // prologue
  {
    const float4* wsrc = g_wpk0 + rank * 6144;
    for (int i = tid; i < 6144; i += 192) wh0s[i] = wsrc[i];
    for (int i = tid; i < 6400; i += 192) {
      int rr = i >> 7, c = i & 127;
      Y_s[rr * 129 + c] = g_y[b * 12800 + (50 * (int)rank + rr) * 128 + c];
    }
    if (tid < 128) {
      h0b[tid] = make_float4(0.f, 0.f, 0.f, 0.f);
      h1b[tid] = make_float4(0.f, 0.f, 0.f, 0.f);
    }
    if (tid == 0) { solS[0] = 0; solG[0] = 0; red[2] = 0.f; red[3] = 0.f; }
  }
  float bh0_r = bhh[col], bi1_r = bih[384 + col], bh1_r = bhh[384 + col];
  int cur_s = 0, cur_g = 0;
  __syncthreads();
  CSYNC();   // both CTAs initialized before any peer DSMEM writes

  const float4* wp1 = g_wpk12 + (rank * 2) * 6144;
  const float4* wp2 = wp1 + 6144;

  for (int t = 0; t < 99; t++) {
    const int p = t & 1;
    float gum_r = 0.f;
    if (tid < 50) gum_r = __ldg(&g_gum[t * 6400 + b * 100 + 50 * (int)rank + tid]);
    float gi_s = __ldg(&g_gi0[(b * 100 + cur_s) * 384 + col]);
    float gi_g = __ldg(&g_gi0[(b * 100 + cur_g) * 384 + col]);

    // ---- layer0 hidden gemv from SMEM (single ascending-k chain per stream) ----
    {
      float as = bh0_r, ag = bh0_r;
      const float4* h0p = h0b + p * 64;
#pragma unroll 16
      for (int kk = 0; kk < 32; kk++) {
        float4 w  = wh0s[kk * 192 + tid];
        float4 ha = h0p[2 * kk], hb = h0p[2 * kk + 1];
        as = fmaf(ha.x, w.x, as); ag = fmaf(ha.y, w.x, ag);
        as = fmaf(ha.z, w.y, as); ag = fmaf(ha.w, w.y, ag);
        as = fmaf(hb.x, w.z, as); ag = fmaf(hb.y, w.z, ag);
        as = fmaf(hb.z, w.w, as); ag = fmaf(hb.w, w.w, ag);
      }
      gi2[tid] = make_float2(gi_s, gi_g);
      gh2[tid] = make_float2(as, ag);
    }
    __syncthreads();
    if (tid < 64) {
      int j = ((int)rank << 6) + tid;
      float2 ir = gi2[tid], iz = gi2[tid + 64], in_ = gi2[tid + 128];
      float2 hr = gh2[tid], hz = gh2[tid + 64], hn  = gh2[tid + 128];
      float2 hp = ((const float2*)(h0b + p * 64))[j];
      float r0 = sigm(ir.x + hr.x), z0 = sigm(iz.x + hz.x), n0 = tanhf(in_.x + r0 * hn.x);
      float r1 = sigm(ir.y + hr.y), z1 = sigm(iz.y + hz.y), n1 = tanhf(in_.y + r1 * hn.y);
      float2 hv = make_float2((1.f - z0) * n0 + z0 * hp.x, (1.f - z1) * n1 + z1 * hp.y);
      ((float2*)(h0b + (1 - p) * 64))[j] = hv;
      uint32_t addr = sbase + ((31028u + (uint32_t)(1 - p) * 256u) << 2) + (uint32_t)j * 8u;
      peer_st_f2(addr, peer, hv.x, hv.y);
    }
    CSYNC();   // #1: full new h0 visible everywhere

    // ---- layer1 gemv: gi = h0_new @ Wi1half, gh = h1_old @ Wh1half ----
    {
      float gis = bi1_r, gig = bi1_r, ghs = bh1_r, ghg = bh1_r;
      const float4* h0n = h0b + (1 - p) * 64;
      const float4* h1o = h1b + p * 64;
#pragma unroll 8
      for (int kk = 0; kk < 32; kk++) {
        float4 wi = wp1[kk * 192 + tid];
        float4 wh = wp2[kk * 192 + tid];
        float4 ha = h0n[2 * kk], hb = h0n[2 * kk + 1];
        float4 ca = h1o[2 * kk], cb = h1o[2 * kk + 1];
        gis = fmaf(ha.x, wi.x, gis); gig = fmaf(ha.y, wi.x, gig);
        gis = fmaf(ha.z, wi.y, gis); gig = fmaf(ha.w, wi.y, gig);
        gis = fmaf(hb.x, wi.z, gis); gig = fmaf(hb.y, wi.z, gig);
        gis = fmaf(hb.z, wi.w, gis); gig = fmaf(hb.w, wi.w, gig);
        ghs = fmaf(ca.x, wh.x, ghs); ghg = fmaf(ca.y, wh.x, ghg);
        ghs = fmaf(ca.z, wh.y, ghs); ghg = fmaf(ca.w, wh.y, ghg);
        ghs = fmaf(cb.x, wh.z, ghs); ghg = fmaf(cb.y, wh.z, ghg);
        ghs = fmaf(cb.z, wh.w, ghs); ghg = fmaf(cb.w, wh.w, ghg);
      }
      gi2[tid] = make_float2(gis, gig);
      gh2[tid] = make_float2(ghs, ghg);
    }
    __syncthreads();
    if (tid < 64) {
      int j = ((int)rank << 6) + tid;
      float2 ir = gi2[tid], iz = gi2[tid + 64], in_ = gi2[tid + 128];
      float2 hr = gh2[tid], hz = gh2[tid + 64], hn  = gh2[tid + 128];
      float2 hp = ((const float2*)(h1b + p * 64))[j];
      float r0 = sigm(ir.x + hr.x), z0 = sigm(iz.x + hz.x), n0 = tanhf(in_.x + r0 * hn.x);
      float r1 = sigm(ir.y + hr.y), z1 = sigm(iz.y + hz.y), n1 = tanhf(in_.y + r1 * hn.y);
      float2 hv = make_float2((1.f - z0) * n0 + z0 * hp.x, (1.f - z1) * n1 + z1 * hp.y);
      ((float2*)(h1b + (1 - p) * 64))[j] = hv;
      uint32_t addr = sbase + ((31540u + (uint32_t)(1 - p) * 256u) << 2) + (uint32_t)j * 8u;
      peer_st_f2(addr, peer, hv.x, hv.y);
    }
    CSYNC();   // #2: full new h1 visible everywhere

    // ---- logits: 50 rows per CTA, thread-per-row ----
    if (tid < 50) {
      const float* yr = Y_s + tid * 129;
      const float2* h1n = (const float2*)(h1b + (1 - p) * 64);
      float ss0 = 0.f, ss1 = 0.f, gg0 = 0.f, gg1 = 0.f;
#pragma unroll 8
      for (int k = 0; k < 128; k += 2) {
        float2 ha = h1n[k], hb = h1n[k + 1];
        float ya = yr[k], yb = yr[k + 1];
        ss0 = fmaf(ha.x, ya, ss0); gg0 = fmaf(ha.y, ya, gg0);
        ss1 = fmaf(hb.x, yb, ss1); gg1 = fmaf(hb.y, yb, gg1);
      }
      float lsv = ss0 + ss1, lgv = gg0 + gg1;
      ls[tid] = lsv;
      ysA[tid] = lsv + gum_r;
      lg[tid] = lgv;
    }
    __syncthreads();

    // ---- local reductions + partial exchange ----
    if (wrp == 0) {            // argmax(ys) over local 50
      float bv = ysA[lane]; int li = lane;
      if (lane + 32 < 50) { float v2 = ysA[lane + 32]; if (v2 > bv) { bv = v2; li = lane + 32; } }
#pragma unroll
      for (int o = 16; o > 0; o >>= 1) {
        float ov = __shfl_xor_sync(0xffffffffu, bv, o);
        int   oi = __shfl_xor_sync(0xffffffffu, li, o);
        if (ov > bv || (ov == bv && oi < li)) { bv = ov; li = oi; }
      }
      if (lane == 0) {
        float lsat = ls[li];
        float gif = __int_as_float((int)rank * 50 + li);
        int base = 32970 + (int)rank * 8;
        part[(int)rank * 8 + 0] = bv;
        part[(int)rank * 8 + 1] = gif;
        part[(int)rank * 8 + 2] = lsat;
        uint32_t a0 = sbase + ((uint32_t)base << 2);
        peer_st_f1(a0,     peer, bv);
        peer_st_f1(a0 + 4, peer, gif);
        peer_st_f1(a0 + 8, peer, lsat);
      }
    } else if (wrp == 1) {     // argmax(lg)
      float bv = lg[lane]; int li = lane;
      if (lane + 32 < 50) { float v2 = lg[lane + 32]; if (v2 > bv) { bv = v2; li = lane + 32; } }
#pragma unroll
      for (int o = 16; o > 0; o >>= 1) {
        float ov = __shfl_xor_sync(0xffffffffu, bv, o);
        int   oi = __shfl_xor_sync(0xffffffffu, li, o);
        if (ov > bv || (ov == bv && oi < li)) { bv = ov; li = oi; }
      }
      if (lane == 0) {
        float gif = __int_as_float((int)rank * 50 + li);
        int base = 32970 + (int)rank * 8;
        part[(int)rank * 8 + 3] = bv;
        part[(int)rank * 8 + 4] = gif;
        uint32_t a0 = sbase + ((uint32_t)base << 2);
        peer_st_f1(a0 + 12, peer, bv);
        peer_st_f1(a0 + 16, peer, gif);
      }
    } else if (wrp == 2) {     // sum exp(ls) over local 50
      float s = expf(ls[lane]);
      if (lane + 32 < 50) s += expf(ls[lane + 32]);
#pragma unroll
      for (int o = 16; o > 0; o >>= 1) s += __shfl_xor_sync(0xffffffffu, s, o);
      if (lane == 0) {
        int base = 32970 + (int)rank * 8;
        part[(int)rank * 8 + 5] = s;
        peer_st_f1(sbase + ((uint32_t)base << 2) + 20, peer, s);
      }
    }
    CSYNC();   // #3: partials exchanged

    // ---- combine (every thread, deterministic & identical) ----
    {
      float v0 = part[0], v1 = part[8];
      int   i0 = __float_as_int(part[1]), i1 = __float_as_int(part[9]);
      float l0 = part[2], l1 = part[10];
      float lsat;
      if (v1 > v0) { cur_s = i1; lsat = l1; } else { cur_s = i0; lsat = l0; }
      float q0 = part[3], q1 = part[11];
      cur_g = (q1 > q0) ? __float_as_int(part[12]) : __float_as_int(part[4]);
      float esum = part[5] + part[13];
      if (rank == 0 && tid == 0) {
        out[OFF_LOGP + b * 99 + t] = lsat - logf(esum);
        solS[t + 1] = cur_s;
        solG[t + 1] = cur_g;
      }
    }
  }

  CSYNC();   // final: histories complete, no more DSMEM traffic
  if (rank == 0) {
    if (tid < 99) {
      atomicAdd(&red[2], dis[b * 10000 + solS[tid] * 100 + solS[tid + 1]]);
      atomicAdd(&red[3], dis[b * 10000 + solG[tid] * 100 + solG[tid + 1]]);
    }
    for (int i = tid; i < 100; i += 192) g_solg[b * 100 + i] = solG[i];
    __syncthreads();
    if (tid == 0) { out[OFF_SD + b] = red[2]; out[OFF_GD + b] = red[3]; }
  }
}

// ---------------- predict_matrix fused ----------------
__global__ void k_pred(const float* __restrict__ dis, const float* __restrict__ We,
                       const float* __restrict__ be, const float* __restrict__ Wc,
                       const float* __restrict__ bc, float* __restrict__ out) {
  int lane = threadIdx.x & 31;
  int gw = (blockIdx.x * blockDim.x + threadIdx.x) >> 5;
  int nw = (gridDim.x * blockDim.x) >> 5;
  float we[4], bee[4], wc0[4], wc1[4];
#pragma unroll
  for (int u = 0; u < 4; u++) {
    int k = lane * 4 + u;
    we[u] = We[k]; bee[u] = be[k]; wc0[u] = Wc[k * 2]; wc1[u] = Wc[k * 2 + 1];
  }
  float bc0 = bc[0], bc1 = bc[1];
  for (int p = gw; p < 640000; p += nw) {
    float d = dis[p];
    float y0 = 0.f, y1 = 0.f;
#pragma unroll
    for (int u = 0; u < 4; u++) {
      float e = fmaxf(fmaf(d, we[u], bee[u]), 0.f);
      y0 = fmaf(e, wc0[u], y0); y1 = fmaf(e, wc1[u], y1);
    }
#pragma unroll
    for (int o = 16; o > 0; o >>= 1) {
      y0 += __shfl_xor_sync(0xffffffffu, y0, o);
      y1 += __shfl_xor_sync(0xffffffffu, y1, o);
    }
    if (lane == 0) {
      y0 += bc0; y1 += bc1;
      float m = fmaxf(y0, y1);
      float e0 = expf(y0 - m), e1 = expf(y1 - m), s = e0 + e1;
      out[OFF_PRED + p * 2]     = e0 / s;
      out[OFF_PRED + p * 2 + 1] = e1 / s;
    }
  }
}

__global__ void k_gzero(float* __restrict__ out) {
  int idx = blockIdx.x * blockDim.x + threadIdx.x;
  if (idx < 640000) out[OFF_GSOL + idx] = 0.f;
}

__global__ void k_gset(float* __restrict__ out) {
  int b = blockIdx.x, t = threadIdx.x;
  if (t < 99) {
    int u = g_solg[b * 100 + t], v = g_solg[b * 100 + t + 1];
    out[OFF_GSOL + b * 10000 + u * 100 + v] = 1.0f;
  }
}

extern "C" void kernel_launch(void* const* d_in, const int* in_sizes, int n_in,
                              void* d_out, int out_size) {
  const float* node   = (const float*)d_in[0];
  const float* demand = (const float*)d_in[1];
  const float* dis    = (const float*)d_in[2];
  const float* Wn0    = (const float*)d_in[3];
  const float* bn0    = (const float*)d_in[4];
  const float* Ws     = (const float*)d_in[5];
  const float* Wngh   = (const float*)d_in[6];
  const float* We     = (const float*)d_in[7];
  const float* be     = (const float*)d_in[8];
  const float* Wih    = (const float*)d_in[9];
  const float* Whh    = (const float*)d_in[10];
  const float* bih    = (const float*)d_in[11];
  const float* bhh    = (const float*)d_in[12];
  const float* Wq     = (const float*)d_in[13];
  const float* Wc     = (const float*)d_in[14];
  const float* bc     = (const float*)d_in[15];
  float* out = (float*)d_out;

  cudaFuncSetAttribute(k_aggr,   cudaFuncAttributeMaxDynamicSharedMemorySize, AGGR2_SMEM);
  cudaFuncSetAttribute(k_y,      cudaFuncAttributeMaxDynamicSharedMemorySize, Y_SMEM);
  cudaFuncSetAttribute(k_decode, cudaFuncAttributeMaxDynamicSharedMemorySize, DEC2_FLOATS * 4);

  k_h0<<<3200, 256>>>(node, demand, Wn0, bn0);
  k_softA<<<1600, 128>>>(dis);
  int src = 0;
  for (int l = 0; l < 3; l++) {
    k_gemm2<<<400, 128>>>(src, Ws + l * 16384, Wngh + l * 16384);
    int dst = 1 - src;
    k_aggr<<<dim3(64, 4), 512, AGGR2_SMEM>>>(dst);
    src = dst;
  }
  // final h in g_buf1
  k_gi0<<<800, 384>>>(Wih, bih);
  k_y<<<800, 128, Y_SMEM>>>(Wq);
  k_pack2<<<576, 256>>>(Wih, Whh);
  k_gumbel<<<99, 256>>>();
  k_decode<<<128, 192, DEC2_FLOATS * 4>>>(dis, bih, bhh, out);
  k_pred<<<1280, 256>>>(dis, We, be, Wc, bc, out);
  k_gzero<<<2500, 256>>>(out);
  k_gset<<<64, 128>>>(out);
}

// round 8
// speedup vs baseline: 3.9564x; 1.0091x over previous
#include <cuda_runtime.h>
#include <stdint.h>

#define OFF_LOGP 0
#define OFF_SD   6336
#define OFF_GD   6400
#define OFF_PRED 6464
#define OFF_GSOL 1286464

__device__ float g_buf0[819200];
__device__ float g_buf1[819200];
__device__ float g_hWs[819200];
__device__ float g_hN[819200];
__device__ float g_A[640000];
__device__ float g_gum[633600];    // 99 * 6400
__device__ int   g_solg[6400];
__device__ float g_gi0[2457600];   // [64][100][384] x@Wih0+bih0
__device__ float g_y[819200];      // [64][100][128] (x@Wq^T)*scale
__device__ float4 g_wpk0[12288];   // Wh0 halves: [q][kk][192]
__device__ float4 g_wpk12[24576];  // [q][m][kk][192], m=0:Wi1 m=1:Wh1

// ---------------- threefry2x32 (exact JAX) ----------------
__device__ __forceinline__ void tf2x32(uint32_t k0, uint32_t k1,
                                       uint32_t c0, uint32_t c1,
                                       uint32_t& o0, uint32_t& o1) {
  uint32_t ks0 = k0, ks1 = k1, ks2 = k0 ^ k1 ^ 0x1BD11BDAu;
  uint32_t x0 = c0 + ks0, x1 = c1 + ks1;
#define TF_RND(R) { x0 += x1; x1 = __funnelshift_l(x1, x1, (R)); x1 ^= x0; }
  TF_RND(13) TF_RND(15) TF_RND(26) TF_RND(6)   x0 += ks1; x1 += ks2 + 1u;
  TF_RND(17) TF_RND(29) TF_RND(16) TF_RND(24)  x0 += ks2; x1 += ks0 + 2u;
  TF_RND(13) TF_RND(15) TF_RND(26) TF_RND(6)   x0 += ks0; x1 += ks1 + 3u;
  TF_RND(17) TF_RND(29) TF_RND(16) TF_RND(24)  x0 += ks1; x1 += ks2 + 4u;
  TF_RND(13) TF_RND(15) TF_RND(26) TF_RND(6)   x0 += ks2; x1 += ks0 + 5u;
#undef TF_RND
  o0 = x0; o1 = x1;
}

// ---------------- cluster / DSMEM helpers ----------------
__device__ __forceinline__ uint32_t smem_u32(const void* p) {
  uint32_t a;
  asm("{ .reg .u64 t; cvta.to.shared.u64 t, %1; cvt.u32.u64 %0, t; }" : "=r"(a) : "l"(p));
  return a;
}
__device__ __forceinline__ uint32_t ctarank() {
  uint32_t r; asm("mov.u32 %0, %%cluster_ctarank;" : "=r"(r)); return r;
}
__device__ __forceinline__ void peer_st_f2(uint32_t laddr, uint32_t peer, float x, float y) {
  uint32_t ra;
  asm("mapa.shared::cluster.u32 %0, %1, %2;" : "=r"(ra) : "r"(laddr), "r"(peer));
  asm volatile("{ .reg .b64 t; mov.b64 t, {%1, %2}; st.shared::cluster.b64 [%0], t; }"
               :: "r"(ra), "f"(x), "f"(y) : "memory");
}
__device__ __forceinline__ void peer_st_f1(uint32_t laddr, uint32_t peer, float x) {
  uint32_t ra;
  asm("mapa.shared::cluster.u32 %0, %1, %2;" : "=r"(ra) : "r"(laddr), "r"(peer));
  asm volatile("st.shared::cluster.b32 [%0], %1;"
               :: "r"(ra), "r"(__float_as_uint(x)) : "memory");
}
#define CSYNC() do { \
  asm volatile("barrier.cluster.arrive.aligned;" ::: "memory"); \
  asm volatile("barrier.cluster.wait.aligned;"  ::: "memory"); } while (0)

// ---------------- h0 = relu([node,demand] @ Wn0 + bn0) ----------------
__global__ void k_h0(const float* __restrict__ node, const float* __restrict__ demand,
                     const float* __restrict__ Wn0, const float* __restrict__ bn0) {
  int idx = blockIdx.x * blockDim.x + threadIdx.x;
  if (idx >= 819200) return;
  int row = idx >> 7, j = idx & 127;
  float v = bn0[j];
  v = fmaf(node[row * 2],     Wn0[j],       v);
  v = fmaf(node[row * 2 + 1], Wn0[128 + j], v);
  v = fmaf(demand[row],       Wn0[256 + j], v);
  g_buf0[idx] = fmaxf(v, 0.f);
}

// ---------------- A = softmax(-dis, -1), warp per row ----------------
__global__ void k_softA(const float* __restrict__ dis) {
  int row  = blockIdx.x * 4 + (threadIdx.x >> 5);
  int lane = threadIdx.x & 31;
  if (row >= 6400) return;
  const float* d = dis + row * 100;
  float v0 = -d[lane], v1 = -d[lane + 32], v2 = -d[lane + 64];
  float v3 = (lane + 96 < 100) ? -d[lane + 96] : -3.4e38f;
  float m = fmaxf(fmaxf(v0, v1), fmaxf(v2, v3));
#pragma unroll
  for (int o = 16; o > 0; o >>= 1) m = fmaxf(m, __shfl_xor_sync(0xffffffffu, m, o));
  float e0 = expf(v0 - m), e1 = expf(v1 - m), e2 = expf(v2 - m);
  float e3 = (lane + 96 < 100) ? expf(v3 - m) : 0.f;
  float s = e0 + e1 + e2 + e3;
#pragma unroll
  for (int o = 16; o > 0; o >>= 1) s += __shfl_xor_sync(0xffffffffu, s, o);
  float* Ar = g_A + row * 100;
  Ar[lane] = e0 / s; Ar[lane + 32] = e1 / s; Ar[lane + 64] = e2 / s;
  if (lane + 96 < 100) Ar[lane + 96] = e3 / s;
}

// ---------------- hWs = h@Ws[l], hN = h@Wngh[l]; 16 rows per block ----------------
__global__ void k_gemm2(int src, const float* __restrict__ W1, const float* __restrict__ W2) {
  const float* h = src ? g_buf1 : g_buf0;
  __shared__ float acts[16][128];
  int j = threadIdx.x;
  int row0 = blockIdx.x * 16;
  for (int i = j; i < 2048; i += 128) acts[i >> 7][i & 127] = h[row0 * 128 + i];
  __syncthreads();
  float aS[16], aN[16];
#pragma unroll
  for (int r = 0; r < 16; r++) { aS[r] = 0.f; aN[r] = 0.f; }
#pragma unroll 4
  for (int k = 0; k < 128; k++) {
    float ws = __ldg(W1 + k * 128 + j);
    float wn = __ldg(W2 + k * 128 + j);
#pragma unroll
    for (int r = 0; r < 16; r++) {
      float a = acts[r][k];
      aS[r] = fmaf(a, ws, aS[r]);
      aN[r] = fmaf(a, wn, aN[r]);
    }
  }
#pragma unroll
  for (int r = 0; r < 16; r++) {
    g_hWs[(row0 + r) * 128 + j] = aS[r];
    g_hN [(row0 + r) * 128 + j] = aN[r];
  }
}

// ---------------- h_next = relu(hWs + A @ hN); grid (64,4), 512 threads ----------------
#define AGGR2_SMEM ((12800 + 2500) * 4)
__global__ void k_aggr(int dst) {
  extern __shared__ float sm[];
  float* hN_s = sm;
  float* A_s  = sm + 12800;
  int b = blockIdx.x, r0 = blockIdx.y * 25, tid = threadIdx.x;
  for (int i = tid; i < 12800; i += 512) hN_s[i] = g_hN[b * 12800 + i];
  for (int i = tid; i < 2500; i += 512)  A_s[i]  = g_A [b * 10000 + r0 * 100 + i];
  __syncthreads();
  float* ho = dst ? g_buf1 : g_buf0;
  int j = tid & 127, g = tid >> 7;
  for (int il = g; il < 25; il += 8) {
    int i2 = il + 4;
    bool two = i2 < 25;
    float a0 = 0.f, a1 = 0.f, c0 = 0.f, c1 = 0.f;
#pragma unroll 10
    for (int p = 0; p < 100; p += 2) {
      float h0v = hN_s[p * 128 + j], h1v = hN_s[(p + 1) * 128 + j];
      a0 = fmaf(A_s[il * 100 + p],     h0v, a0);
      a1 = fmaf(A_s[il * 100 + p + 1], h1v, a1);
      if (two) {
        c0 = fmaf(A_s[i2 * 100 + p],     h0v, c0);
        c1 = fmaf(A_s[i2 * 100 + p + 1], h1v, c1);
      }
    }
    int row = b * 100 + r0 + il;
    ho[row * 128 + j] = fmaxf(g_hWs[row * 128 + j] + a0 + a1, 0.f);
    if (two)
      ho[(row + 4) * 128 + j] = fmaxf(g_hWs[(row + 4) * 128 + j] + c0 + c1, 0.f);
  }
}

// ---------------- precompute Gi0 = x @ Wih0 + bih0 ----------------
__global__ void k_gi0(const float* __restrict__ Wih, const float* __restrict__ bih) {
  __shared__ float acts[8][128];
  int o = threadIdx.x;
  int row0 = blockIdx.x * 8;
  for (int i = o; i < 1024; i += 384) acts[i >> 7][i & 127] = g_buf1[row0 * 128 + i];
  __syncthreads();
  float a[8];
  float bv = bih[o];
#pragma unroll
  for (int r = 0; r < 8; r++) a[r] = bv;
#pragma unroll 8
  for (int k = 0; k < 128; k++) {
    float w = __ldg(Wih + k * 384 + o);
#pragma unroll
    for (int r = 0; r < 8; r++) a[r] = fmaf(acts[r][k], w, a[r]);
  }
#pragma unroll
  for (int r = 0; r < 8; r++) g_gi0[(row0 + r) * 384 + o] = a[r];
}

// ---------------- precompute Y = (x @ Wq^T)*scale ----------------
#define Y_SMEM ((129 * 128 + 1024) * 4)
__global__ void k_y(const float* __restrict__ Wq) {
  extern __shared__ float sm[];
  float* wq_t = sm;
  float* acts = sm + 16512;
  int tid = threadIdx.x;
  int row0 = blockIdx.x * 8;
  for (int i = tid; i < 16384; i += 128) {
    int k = i >> 7, j = i & 127;
    wq_t[j * 129 + k] = Wq[i];
  }
  for (int i = tid; i < 1024; i += 128) acts[i] = g_buf1[row0 * 128 + i];
  __syncthreads();
  const float scale = (float)(1.0 / (double)sqrtf(128.0f));
  int k = tid;
  float a[8];
#pragma unroll
  for (int r = 0; r < 8; r++) a[r] = 0.f;
#pragma unroll 4
  for (int j = 0; j < 128; j++) {
    float w = wq_t[j * 129 + k];
#pragma unroll
    for (int r = 0; r < 8; r++) a[r] = fmaf(acts[r * 128 + j], w, a[r]);
  }
#pragma unroll
  for (int r = 0; r < 8; r++) g_y[(row0 + r) * 128 + k] = a[r] * scale;
}

// ---------------- pack split weights ----------------
__global__ void k_pack2(const float* __restrict__ Wih, const float* __restrict__ Whh) {
  int idx = blockIdx.x * blockDim.x + threadIdx.x;
  if (idx >= 147456) return;
  if (idx < 49152) {
    int f4 = idx >> 2, u = idx & 3;
    int q = f4 / 6144, r4 = f4 % 6144;
    int kk = r4 / 192, o = r4 % 192;
    int col = (o >> 6) * 128 + (q << 6) + (o & 63);
    ((float*)g_wpk0)[idx] = Whh[(4 * kk + u) * 384 + col];
  } else {
    int i2 = idx - 49152;
    int f4 = i2 >> 2, u = i2 & 3;
    int unit = f4 / 6144, r4 = f4 % 6144;
    int q = unit >> 1, m = unit & 1;
    int kk = r4 / 192, o = r4 % 192;
    int col = (o >> 6) * 128 + (q << 6) + (o & 63);
    const float* src = m ? (Whh + 49152) : (Wih + 49152);
    ((float*)g_wpk12)[i2] = src[(4 * kk + u) * 384 + col];
  }
}

// ---------------- gumbel precompute ----------------
__global__ void k_gumbel() {
  int t = blockIdx.x;
  __shared__ uint32_t sk0, sk1;
  if (threadIdx.x == 0) {
    uint32_t k0 = 0u, k1 = 42u, a, b;
    tf2x32(k0, k1, 0u, 0u, a, b); k0 = a; k1 = b;
    for (int i = 0; i < t; i++) { tf2x32(k0, k1, 0u, 0u, a, b); k0 = a; k1 = b; }
    tf2x32(k0, k1, 0u, 1u, a, b); sk0 = a; sk1 = b;
  }
  __syncthreads();
  const float TINY = 1.17549435e-38f;
  uint32_t s0 = sk0, s1 = sk1;
  for (int i = threadIdx.x; i < 6400; i += blockDim.x) {
    uint32_t o0, o1;
    tf2x32(s0, s1, 0u, (uint32_t)i, o0, o1);
    uint32_t bits = o0 ^ o1;
    float f = __uint_as_float((bits >> 9) | 0x3f800000u) - 1.0f;
    float u = fmaxf(TINY, f + TINY);
    g_gum[t * 6400 + i] = -logf(-logf(u));
  }
}

__device__ __forceinline__ float sigm(float x) { return 1.f / (1.f + expf(-x)); }

// ---------------- cluster-of-2 decoder, Wh0+Wi1 SMEM-resident, Wh1 prefetch-streamed ----
// smem float offsets:
#define SOF_WH0   0        // float4[6144]
#define SOF_WP1   24576    // float4[6144]
#define SOF_Y     49152    // [50*129] = 6450
#define SOF_H0B   55604    // float4[2][64] = 512 floats
#define SOF_H1B   56116    // float4[2][64]
#define SOF_GI2   56628    // float2[192] = 384
#define SOF_GH2   57012    // float2[192]
#define SOF_LS    57396
#define SOF_LG    57446
#define SOF_YSA   57496
#define SOF_PART  57546    // 16
#define SOF_SOLS  57562
#define SOF_SOLG  57662
#define SOF_RED   57762
#define DEC2_FLOATS 57766
__global__ void __cluster_dims__(2, 1, 1) __launch_bounds__(192, 1) k_decode(
    const float* __restrict__ dis, const float* __restrict__ bih,
    const float* __restrict__ bhh, float* __restrict__ out) {
  extern __shared__ float sm[];
  const int tid = threadIdx.x;
  const int b = blockIdx.x >> 1;
  const uint32_t rank = ctarank();
  const uint32_t peer = rank ^ 1u;
  const int lane = tid & 31, wrp = tid >> 5;
  const int col = ((tid >> 6) << 7) + ((int)rank << 6) + (tid & 63);

  float4* wh0s = (float4*)(sm + SOF_WH0);
  float4* wp1s = (float4*)(sm + SOF_WP1);
  float*  Y_s  = sm + SOF_Y;
  float4* h0b  = (float4*)(sm + SOF_H0B);
  float4* h1b  = (float4*)(sm + SOF_H1B);
  float2* gi2  = (float2*)(sm + SOF_GI2);
  float2* gh2  = (float2*)(sm + SOF_GH2);
  float*  ls   = sm + SOF_LS;
  float*  lg   = sm + SOF_LG;
  float*  ysA  = sm + SOF_YSA;
  float*  part = sm + SOF_PART;
  int*    solS = (int*)(sm + SOF_SOLS);
  int*    solG = (int*)(sm + SOF_SOLG);
  float*  red  = sm + SOF_RED;

  const uint32_t sbase = smem_u32(sm);

  // prologue: stage resident weights + Y
  {
    const float4* w0src = g_wpk0 + rank * 6144;
    const float4* w1src = g_wpk12 + (rank * 2) * 6144;
    for (int i = tid; i < 6144; i += 192) { wh0s[i] = w0src[i]; wp1s[i] = w1src[i]; }
    for (int i = tid; i < 6400; i += 192) {
      int rr = i >> 7, c = i & 127;
      Y_s[rr * 129 + c] = g_y[b * 12800 + (50 * (int)rank + rr) * 128 + c];
    }
    if (tid < 128) {
      h0b[tid] = make_float4(0.f, 0.f, 0.f, 0.f);
      h1b[tid] = make_float4(0.f, 0.f, 0.f, 0.f);
    }
    if (tid == 0) { solS[0] = 0; solG[0] = 0; red[2] = 0.f; red[3] = 0.f; }
  }
  float bh0_r = bhh[col], bi1_r = bih[384 + col], bh1_r = bhh[384 + col];
  int cur_s = 0, cur_g = 0;
  __syncthreads();
  CSYNC();

  const float4* wp2g = g_wpk12 + (rank * 2 + 1) * 6144;   // Wh1 half (streamed)

  for (int t = 0; t < 99; t++) {
    const int p = t & 1;
    float gum_r = 0.f;
    if (tid < 50) gum_r = __ldg(&g_gum[t * 6400 + b * 100 + 50 * (int)rank + tid]);
    float gi_s = __ldg(&g_gi0[(b * 100 + cur_s) * 384 + col]);
    float gi_g = __ldg(&g_gi0[(b * 100 + cur_g) * 384 + col]);

    // ---- gh1 gemv FIRST: streams Wh1 from L2; input h1_old available now ----
    float ghs1 = bh1_r, ghg1 = bh1_r;
    {
      const float4* h1o = h1b + p * 64;
#pragma unroll 8
      for (int kk = 0; kk < 32; kk++) {
        float4 wh = wp2g[kk * 192 + tid];
        float4 ca = h1o[2 * kk], cb = h1o[2 * kk + 1];
        ghs1 = fmaf(ca.x, wh.x, ghs1); ghg1 = fmaf(ca.y, wh.x, ghg1);
        ghs1 = fmaf(ca.z, wh.y, ghs1); ghg1 = fmaf(ca.w, wh.y, ghg1);
        ghs1 = fmaf(cb.x, wh.z, ghs1); ghg1 = fmaf(cb.y, wh.z, ghg1);
        ghs1 = fmaf(cb.z, wh.w, ghs1); ghg1 = fmaf(cb.w, wh.w, ghg1);
      }
    }

    // ---- layer0 hidden gemv from SMEM ----
    {
      float as = bh0_r, ag = bh0_r;
      const float4* h0p = h0b + p * 64;
#pragma unroll 16
      for (int kk = 0; kk < 32; kk++) {
        float4 w  = wh0s[kk * 192 + tid];
        float4 ha = h0p[2 * kk], hb = h0p[2 * kk + 1];
        as = fmaf(ha.x, w.x, as); ag = fmaf(ha.y, w.x, ag);
        as = fmaf(ha.z, w.y, as); ag = fmaf(ha.w, w.y, ag);
        as = fmaf(hb.x, w.z, as); ag = fmaf(hb.y, w.z, ag);
        as = fmaf(hb.z, w.w, as); ag = fmaf(hb.w, w.w, ag);
      }
      gi2[tid] = make_float2(gi_s, gi_g);
      gh2[tid] = make_float2(as, ag);
    }
    __syncthreads();
    if (tid < 64) {
      int j = ((int)rank << 6) + tid;
      float2 ir = gi2[tid], iz = gi2[tid + 64], in_ = gi2[tid + 128];
      float2 hr = gh2[tid], hz = gh2[tid + 64], hn  = gh2[tid + 128];
      float2 hp = ((const float2*)(h0b + p * 64))[j];
      float r0 = sigm(ir.x + hr.x), z0 = sigm(iz.x + hz.x), n0 = tanhf(in_.x + r0 * hn.x);
      float r1 = sigm(ir.y + hr.y), z1 = sigm(iz.y + hz.y), n1 = tanhf(in_.y + r1 * hn.y);
      float2 hv = make_float2((1.f - z0) * n0 + z0 * hp.x, (1.f - z1) * n1 + z1 * hp.y);
      ((float2*)(h0b + (1 - p) * 64))[j] = hv;
      uint32_t addr = sbase + (((uint32_t)SOF_H0B + (uint32_t)(1 - p) * 256u) << 2) + (uint32_t)j * 8u;
      peer_st_f2(addr, peer, hv.x, hv.y);
    }
    CSYNC();   // #1: full new h0 visible everywhere

    // ---- gi1 gemv from SMEM-resident Wi1 half ----
    {
      float gis = bi1_r, gig = bi1_r;
      const float4* h0n = h0b + (1 - p) * 64;
#pragma unroll 16
      for (int kk = 0; kk < 32; kk++) {
        float4 wi = wp1s[kk * 192 + tid];
        float4 ha = h0n[2 * kk], hb = h0n[2 * kk + 1];
        gis = fmaf(ha.x, wi.x, gis); gig = fmaf(ha.y, wi.x, gig);
        gis = fmaf(ha.z, wi.y, gis); gig = fmaf(ha.w, wi.y, gig);
        gis = fmaf(hb.x, wi.z, gis); gig = fmaf(hb.y, wi.z, gig);
        gis = fmaf(hb.z, wi.w, gis); gig = fmaf(hb.w, wi.w, gig);
      }
      gi2[tid] = make_float2(gis, gig);
      gh2[tid] = make_float2(ghs1, ghg1);
    }
    __syncthreads();
    if (tid < 64) {
      int j = ((int)rank << 6) + tid;
      float2 ir = gi2[tid], iz = gi2[tid + 64], in_ = gi2[tid + 128];
      float2 hr = gh2[tid], hz = gh2[tid + 64], hn  = gh2[tid + 128];
      float2 hp = ((const float2*)(h1b + p * 64))[j];
      float r0 = sigm(ir.x + hr.x), z0 = sigm(iz.x + hz.x), n0 = tanhf(in_.x + r0 * hn.x);
      float r1 = sigm(ir.y + hr.y), z1 = sigm(iz.y + hz.y), n1 = tanhf(in_.y + r1 * hn.y);
      float2 hv = make_float2((1.f - z0) * n0 + z0 * hp.x, (1.f - z1) * n1 + z1 * hp.y);
      ((float2*)(h1b + (1 - p) * 64))[j] = hv;
      uint32_t addr = sbase + (((uint32_t)SOF_H1B + (uint32_t)(1 - p) * 256u) << 2) + (uint32_t)j * 8u;
      peer_st_f2(addr, peer, hv.x, hv.y);
    }
    CSYNC();   // #2: full new h1 visible everywhere

    // ---- logits: 50 rows per CTA, thread-per-row ----
    if (tid < 50) {
      const float* yr = Y_s + tid * 129;
      const float2* h1n = (const float2*)(h1b + (1 - p) * 64);
      float ss0 = 0.f, ss1 = 0.f, gg0 = 0.f, gg1 = 0.f;
#pragma unroll 8
      for (int k = 0; k < 128; k += 2) {
        float2 ha = h1n[k], hb = h1n[k + 1];
        float ya = yr[k], yb = yr[k + 1];
        ss0 = fmaf(ha.x, ya, ss0); gg0 = fmaf(ha.y, ya, gg0);
        ss1 = fmaf(hb.x, yb, ss1); gg1 = fmaf(hb.y, yb, gg1);
      }
      float lsv = ss0 + ss1, lgv = gg0 + gg1;
      ls[tid] = lsv;
      ysA[tid] = lsv + gum_r;
      lg[tid] = lgv;
    }
    __syncthreads();

    // ---- local reductions + partial exchange ----
    if (wrp == 0) {
      float bv = ysA[lane]; int li = lane;
      if (lane + 32 < 50) { float v2 = ysA[lane + 32]; if (v2 > bv) { bv = v2; li = lane + 32; } }
#pragma unroll
      for (int o = 16; o > 0; o >>= 1) {
        float ov = __shfl_xor_sync(0xffffffffu, bv, o);
        int   oi = __shfl_xor_sync(0xffffffffu, li, o);
        if (ov > bv || (ov == bv && oi < li)) { bv = ov; li = oi; }
      }
      if (lane == 0) {
        float lsat = ls[li];
        float gif = __int_as_float((int)rank * 50 + li);
        part[(int)rank * 8 + 0] = bv;
        part[(int)rank * 8 + 1] = gif;
        part[(int)rank * 8 + 2] = lsat;
        uint32_t a0 = sbase + (((uint32_t)SOF_PART + (uint32_t)rank * 8u) << 2);
        peer_st_f1(a0,     peer, bv);
        peer_st_f1(a0 + 4, peer, gif);
        peer_st_f1(a0 + 8, peer, lsat);
      }
    } else if (wrp == 1) {
      float bv = lg[lane]; int li = lane;
      if (lane + 32 < 50) { float v2 = lg[lane + 32]; if (v2 > bv) { bv = v2; li = lane + 32; } }
#pragma unroll
      for (int o = 16; o > 0; o >>= 1) {
        float ov = __shfl_xor_sync(0xffffffffu, bv, o);
        int   oi = __shfl_xor_sync(0xffffffffu, li, o);
        if (ov > bv || (ov == bv && oi < li)) { bv = ov; li = oi; }
      }
      if (lane == 0) {
        float gif = __int_as_float((int)rank * 50 + li);
        part[(int)rank * 8 + 3] = bv;
        part[(int)rank * 8 + 4] = gif;
        uint32_t a0 = sbase + (((uint32_t)SOF_PART + (uint32_t)rank * 8u) << 2);
        peer_st_f1(a0 + 12, peer, bv);
        peer_st_f1(a0 + 16, peer, gif);
      }
    } else if (wrp == 2) {
      float s = expf(ls[lane]);
      if (lane + 32 < 50) s += expf(ls[lane + 32]);
#pragma unroll
      for (int o = 16; o > 0; o >>= 1) s += __shfl_xor_sync(0xffffffffu, s, o);
      if (lane == 0) {
        part[(int)rank * 8 + 5] = s;
        uint32_t a0 = sbase + (((uint32_t)SOF_PART + (uint32_t)rank * 8u) << 2);
        peer_st_f1(a0 + 20, peer, s);
      }
    }
    CSYNC();   // #3: partials exchanged

    // ---- combine ----
    {
      float v0 = part[0], v1 = part[8];
      int   i0 = __float_as_int(part[1]), i1 = __float_as_int(part[9]);
      float l0 = part[2], l1 = part[10];
      float lsat;
      if (v1 > v0) { cur_s = i1; lsat = l1; } else { cur_s = i0; lsat = l0; }
      float q0 = part[3], q1 = part[11];
      cur_g = (q1 > q0) ? __float_as_int(part[12]) : __float_as_int(part[4]);
      float esum = part[5] + part[13];
      if (rank == 0 && tid == 0) {
        out[OFF_LOGP + b * 99 + t] = lsat - logf(esum);
        solS[t + 1] = cur_s;
        solG[t + 1] = cur_g;
      }
    }
  }

  CSYNC();
  if (rank == 0) {
    if (tid < 99) {
      atomicAdd(&red[2], dis[b * 10000 + solS[tid] * 100 + solS[tid + 1]]);
      atomicAdd(&red[3], dis[b * 10000 + solG[tid] * 100 + solG[tid + 1]]);
    }
    for (int i = tid; i < 100; i += 192) g_solg[b * 100 + i] = solG[i];
    __syncthreads();
    if (tid == 0) { out[OFF_SD + b] = red[2]; out[OFF_GD + b] = red[3]; }
  }
}

// ---------------- predict_matrix fused ----------------
__global__ void k_pred(const float* __restrict__ dis, const float* __restrict__ We,
                       const float* __restrict__ be, const float* __restrict__ Wc,
                       const float* __restrict__ bc, float* __restrict__ out) {
  int lane = threadIdx.x & 31;
  int gw = (blockIdx.x * blockDim.x + threadIdx.x) >> 5;
  int nw = (gridDim.x * blockDim.x) >> 5;
  float we[4], bee[4], wc0[4], wc1[4];
#pragma unroll
  for (int u = 0; u < 4; u++) {
    int k = lane * 4 + u;
    we[u] = We[k]; bee[u] = be[k]; wc0[u] = Wc[k * 2]; wc1[u] = Wc[k * 2 + 1];
  }
  float bc0 = bc[0], bc1 = bc[1];
  for (int p = gw; p < 640000; p += nw) {
    float d = dis[p];
    float y0 = 0.f, y1 = 0.f;
#pragma unroll
    for (int u = 0; u < 4; u++) {
      float e = fmaxf(fmaf(d, we[u], bee[u]), 0.f);
      y0 = fmaf(e, wc0[u], y0); y1 = fmaf(e, wc1[u], y1);
    }
#pragma unroll
    for (int o = 16; o > 0; o >>= 1) {
      y0 += __shfl_xor_sync(0xffffffffu, y0, o);
      y1 += __shfl_xor_sync(0xffffffffu, y1, o);
    }
    if (lane == 0) {
      y0 += bc0; y1 += bc1;
      float m = fmaxf(y0, y1);
      float e0 = expf(y0 - m), e1 = expf(y1 - m), s = e0 + e1;
      out[OFF_PRED + p * 2]     = e0 / s;
      out[OFF_PRED + p * 2 + 1] = e1 / s;
    }
  }
}

__global__ void k_gzero(float* __restrict__ out) {
  int idx = blockIdx.x * blockDim.x + threadIdx.x;
  if (idx < 640000) out[OFF_GSOL + idx] = 0.f;
}

__global__ void k_gset(float* __restrict__ out) {
  int b = blockIdx.x, t = threadIdx.x;
  if (t < 99) {
    int u = g_solg[b * 100 + t], v = g_solg[b * 100 + t + 1];
    out[OFF_GSOL + b * 10000 + u * 100 + v] = 1.0f;
  }
}

extern "C" void kernel_launch(void* const* d_in, const int* in_sizes, int n_in,
                              void* d_out, int out_size) {
  const float* node   = (const float*)d_in[0];
  const float* demand = (const float*)d_in[1];
  const float* dis    = (const float*)d_in[2];
  const float* Wn0    = (const float*)d_in[3];
  const float* bn0    = (const float*)d_in[4];
  const float* Ws     = (const float*)d_in[5];
  const float* Wngh   = (const float*)d_in[6];
  const float* We     = (const float*)d_in[7];
  const float* be     = (const float*)d_in[8];
  const float* Wih    = (const float*)d_in[9];
  const float* Whh    = (const float*)d_in[10];
  const float* bih    = (const float*)d_in[11];
  const float* bhh    = (const float*)d_in[12];
  const float* Wq     = (const float*)d_in[13];
  const float* Wc     = (const float*)d_in[14];
  const float* bc     = (const float*)d_in[15];
  float* out = (float*)d_out;

  cudaFuncSetAttribute(k_aggr,   cudaFuncAttributeMaxDynamicSharedMemorySize, AGGR2_SMEM);
  cudaFuncSetAttribute(k_y,      cudaFuncAttributeMaxDynamicSharedMemorySize, Y_SMEM);
  cudaFuncSetAttribute(k_decode, cudaFuncAttributeMaxDynamicSharedMemorySize, DEC2_FLOATS * 4);

  k_h0<<<3200, 256>>>(node, demand, Wn0, bn0);
  k_softA<<<1600, 128>>>(dis);
  int src = 0;
  for (int l = 0; l < 3; l++) {
    k_gemm2<<<400, 128>>>(src, Ws + l * 16384, Wngh + l * 16384);
    int dst = 1 - src;
    k_aggr<<<dim3(64, 4), 512, AGGR2_SMEM>>>(dst);
    src = dst;
  }
  // final h in g_buf1
  k_gi0<<<800, 384>>>(Wih, bih);
  k_y<<<800, 128, Y_SMEM>>>(Wq);
  k_pack2<<<576, 256>>>(Wih, Whh);
  k_gumbel<<<99, 256>>>();
  k_decode<<<128, 192, DEC2_FLOATS * 4>>>(dis, bih, bhh, out);
  k_pred<<<1280, 256>>>(dis, We, be, Wc, bc, out);
  k_gzero<<<2500, 256>>>(out);
  k_gset<<<64, 128>>>(out);
}

// round 9
// speedup vs baseline: 4.1316x; 1.0443x over previous
#include <cuda_runtime.h>
#include <stdint.h>

#define OFF_LOGP 0
#define OFF_SD   6336
#define OFF_GD   6400
#define OFF_PRED 6464
#define OFF_GSOL 1286464

__device__ float g_buf0[819200];
__device__ float g_buf1[819200];
__device__ float g_hWs[819200];
__device__ float g_hN[819200];
__device__ float g_A[640000];
__device__ float g_gum[633600];    // 99 * 6400
__device__ int   g_solg[6400];
__device__ float g_gi0[2457600];   // [64][100][384] x@Wih0+bih0
__device__ float g_y[819200];      // [64][100][128] (x@Wq^T)*scale
__device__ float4 g_wpk0[12288];   // Wh0 halves: [q][kk][192]
__device__ float4 g_wpk12[24576];  // [q][m][kk][192], m=0:Wi1 m=1:Wh1

// ---------------- threefry2x32 (exact JAX) ----------------
__device__ __forceinline__ void tf2x32(uint32_t k0, uint32_t k1,
                                       uint32_t c0, uint32_t c1,
                                       uint32_t& o0, uint32_t& o1) {
  uint32_t ks0 = k0, ks1 = k1, ks2 = k0 ^ k1 ^ 0x1BD11BDAu;
  uint32_t x0 = c0 + ks0, x1 = c1 + ks1;
#define TF_RND(R) { x0 += x1; x1 = __funnelshift_l(x1, x1, (R)); x1 ^= x0; }
  TF_RND(13) TF_RND(15) TF_RND(26) TF_RND(6)   x0 += ks1; x1 += ks2 + 1u;
  TF_RND(17) TF_RND(29) TF_RND(16) TF_RND(24)  x0 += ks2; x1 += ks0 + 2u;
  TF_RND(13) TF_RND(15) TF_RND(26) TF_RND(6)   x0 += ks0; x1 += ks1 + 3u;
  TF_RND(17) TF_RND(29) TF_RND(16) TF_RND(24)  x0 += ks1; x1 += ks2 + 4u;
  TF_RND(13) TF_RND(15) TF_RND(26) TF_RND(6)   x0 += ks2; x1 += ks0 + 5u;
#undef TF_RND
  o0 = x0; o1 = x1;
}

// ---------------- cluster / DSMEM helpers ----------------
__device__ __forceinline__ uint32_t smem_u32(const void* p) {
  uint32_t a;
  asm("{ .reg .u64 t; cvta.to.shared.u64 t, %1; cvt.u32.u64 %0, t; }" : "=r"(a) : "l"(p));
  return a;
}
__device__ __forceinline__ uint32_t ctarank() {
  uint32_t r; asm("mov.u32 %0, %%cluster_ctarank;" : "=r"(r)); return r;
}
__device__ __forceinline__ void peer_st_f2(uint32_t laddr, uint32_t peer, float x, float y) {
  uint32_t ra;
  asm("mapa.shared::cluster.u32 %0, %1, %2;" : "=r"(ra) : "r"(laddr), "r"(peer));
  asm volatile("{ .reg .b64 t; mov.b64 t, {%1, %2}; st.shared::cluster.b64 [%0], t; }"
               :: "r"(ra), "f"(x), "f"(y) : "memory");
}
#define CSYNC() do { \
  asm volatile("barrier.cluster.arrive.aligned;" ::: "memory"); \
  asm volatile("barrier.cluster.wait.aligned;"  ::: "memory"); } while (0)

// ---------------- h0 = relu([node,demand] @ Wn0 + bn0) ----------------
__global__ void k_h0(const float* __restrict__ node, const float* __restrict__ demand,
                     const float* __restrict__ Wn0, const float* __restrict__ bn0) {
  int idx = blockIdx.x * blockDim.x + threadIdx.x;
  if (idx >= 819200) return;
  int row = idx >> 7, j = idx & 127;
  float v = bn0[j];
  v = fmaf(node[row * 2],     Wn0[j],       v);
  v = fmaf(node[row * 2 + 1], Wn0[128 + j], v);
  v = fmaf(demand[row],       Wn0[256 + j], v);
  g_buf0[idx] = fmaxf(v, 0.f);
}

// ---------------- A = softmax(-dis, -1), warp per row ----------------
__global__ void k_softA(const float* __restrict__ dis) {
  int row  = blockIdx.x * 4 + (threadIdx.x >> 5);
  int lane = threadIdx.x & 31;
  if (row >= 6400) return;
  const float* d = dis + row * 100;
  float v0 = -d[lane], v1 = -d[lane + 32], v2 = -d[lane + 64];
  float v3 = (lane + 96 < 100) ? -d[lane + 96] : -3.4e38f;
  float m = fmaxf(fmaxf(v0, v1), fmaxf(v2, v3));
#pragma unroll
  for (int o = 16; o > 0; o >>= 1) m = fmaxf(m, __shfl_xor_sync(0xffffffffu, m, o));
  float e0 = expf(v0 - m), e1 = expf(v1 - m), e2 = expf(v2 - m);
  float e3 = (lane + 96 < 100) ? expf(v3 - m) : 0.f;
  float s = e0 + e1 + e2 + e3;
#pragma unroll
  for (int o = 16; o > 0; o >>= 1) s += __shfl_xor_sync(0xffffffffu, s, o);
  float* Ar = g_A + row * 100;
  Ar[lane] = e0 / s; Ar[lane + 32] = e1 / s; Ar[lane + 64] = e2 / s;
  if (lane + 96 < 100) Ar[lane + 96] = e3 / s;
}

// ---------------- hWs = h@Ws[l], hN = h@Wngh[l]; 16 rows per block ----------------
__global__ void k_gemm2(int src, const float* __restrict__ W1, const float* __restrict__ W2) {
  const float* h = src ? g_buf1 : g_buf0;
  __shared__ float acts[16][128];
  int j = threadIdx.x;
  int row0 = blockIdx.x * 16;
  for (int i = j; i < 2048; i += 128) acts[i >> 7][i & 127] = h[row0 * 128 + i];
  __syncthreads();
  float aS[16], aN[16];
#pragma unroll
  for (int r = 0; r < 16; r++) { aS[r] = 0.f; aN[r] = 0.f; }
#pragma unroll 4
  for (int k = 0; k < 128; k++) {
    float ws = __ldg(W1 + k * 128 + j);
    float wn = __ldg(W2 + k * 128 + j);
#pragma unroll
    for (int r = 0; r < 16; r++) {
      float a = acts[r][k];
      aS[r] = fmaf(a, ws, aS[r]);
      aN[r] = fmaf(a, wn, aN[r]);
    }
  }
#pragma unroll
  for (int r = 0; r < 16; r++) {
    g_hWs[(row0 + r) * 128 + j] = aS[r];
    g_hN [(row0 + r) * 128 + j] = aN[r];
  }
}

// ---------------- h_next = relu(hWs + A @ hN); grid (64,4), 512 threads ----------------
#define AGGR2_SMEM ((12800 + 2500) * 4)
__global__ void k_aggr(int dst) {
  extern __shared__ float sm[];
  float* hN_s = sm;
  float* A_s  = sm + 12800;
  int b = blockIdx.x, r0 = blockIdx.y * 25, tid = threadIdx.x;
  for (int i = tid; i < 12800; i += 512) hN_s[i] = g_hN[b * 12800 + i];
  for (int i = tid; i < 2500; i += 512)  A_s[i]  = g_A [b * 10000 + r0 * 100 + i];
  __syncthreads();
  float* ho = dst ? g_buf1 : g_buf0;
  int j = tid & 127, g = tid >> 7;
  for (int il = g; il < 25; il += 8) {
    int i2 = il + 4;
    bool two = i2 < 25;
    float a0 = 0.f, a1 = 0.f, c0 = 0.f, c1 = 0.f;
#pragma unroll 10
    for (int p = 0; p < 100; p += 2) {
      float h0v = hN_s[p * 128 + j], h1v = hN_s[(p + 1) * 128 + j];
      a0 = fmaf(A_s[il * 100 + p],     h0v, a0);
      a1 = fmaf(A_s[il * 100 + p + 1], h1v, a1);
      if (two) {
        c0 = fmaf(A_s[i2 * 100 + p],     h0v, c0);
        c1 = fmaf(A_s[i2 * 100 + p + 1], h1v, c1);
      }
    }
    int row = b * 100 + r0 + il;
    ho[row * 128 + j] = fmaxf(g_hWs[row * 128 + j] + a0 + a1, 0.f);
    if (two)
      ho[(row + 4) * 128 + j] = fmaxf(g_hWs[(row + 4) * 128 + j] + c0 + c1, 0.f);
  }
}

// ---------------- precompute Gi0 = x @ Wih0 + bih0 ----------------
__global__ void k_gi0(const float* __restrict__ Wih, const float* __restrict__ bih) {
  __shared__ float acts[8][128];
  int o = threadIdx.x;
  int row0 = blockIdx.x * 8;
  for (int i = o; i < 1024; i += 384) acts[i >> 7][i & 127] = g_buf1[row0 * 128 + i];
  __syncthreads();
  float a[8];
  float bv = bih[o];
#pragma unroll
  for (int r = 0; r < 8; r++) a[r] = bv;
#pragma unroll 8
  for (int k = 0; k < 128; k++) {
    float w = __ldg(Wih + k * 384 + o);
#pragma unroll
    for (int r = 0; r < 8; r++) a[r] = fmaf(acts[r][k], w, a[r]);
  }
#pragma unroll
  for (int r = 0; r < 8; r++) g_gi0[(row0 + r) * 384 + o] = a[r];
}

// ---------------- precompute Y = (x @ Wq^T)*scale ----------------
#define Y_SMEM ((129 * 128 + 1024) * 4)
__global__ void k_y(const float* __restrict__ Wq) {
  extern __shared__ float sm[];
  float* wq_t = sm;
  float* acts = sm + 16512;
  int tid = threadIdx.x;
  int row0 = blockIdx.x * 8;
  for (int i = tid; i < 16384; i += 128) {
    int k = i >> 7, j = i & 127;
    wq_t[j * 129 + k] = Wq[i];
  }
  for (int i = tid; i < 1024; i += 128) acts[i] = g_buf1[row0 * 128 + i];
  __syncthreads();
  const float scale = (float)(1.0 / (double)sqrtf(128.0f));
  int k = tid;
  float a[8];
#pragma unroll
  for (int r = 0; r < 8; r++) a[r] = 0.f;
#pragma unroll 4
  for (int j = 0; j < 128; j++) {
    float w = wq_t[j * 129 + k];
#pragma unroll
    for (int r = 0; r < 8; r++) a[r] = fmaf(acts[r * 128 + j], w, a[r]);
  }
#pragma unroll
  for (int r = 0; r < 8; r++) g_y[(row0 + r) * 128 + k] = a[r] * scale;
}

// ---------------- pack split weights ----------------
__global__ void k_pack2(const float* __restrict__ Wih, const float* __restrict__ Whh) {
  int idx = blockIdx.x * blockDim.x + threadIdx.x;
  if (idx >= 147456) return;
  if (idx < 49152) {
    int f4 = idx >> 2, u = idx & 3;
    int q = f4 / 6144, r4 = f4 % 6144;
    int kk = r4 / 192, o = r4 % 192;
    int col = (o >> 6) * 128 + (q << 6) + (o & 63);
    ((float*)g_wpk0)[idx] = Whh[(4 * kk + u) * 384 + col];
  } else {
    int i2 = idx - 49152;
    int f4 = i2 >> 2, u = i2 & 3;
    int unit = f4 / 6144, r4 = f4 % 6144;
    int q = unit >> 1, m = unit & 1;
    int kk = r4 / 192, o = r4 % 192;
    int col = (o >> 6) * 128 + (q << 6) + (o & 63);
    const float* src = m ? (Whh + 49152) : (Wih + 49152);
    ((float*)g_wpk12)[i2] = src[(4 * kk + u) * 384 + col];
  }
}

// ---------------- gumbel precompute ----------------
__global__ void k_gumbel() {
  int t = blockIdx.x;
  __shared__ uint32_t sk0, sk1;
  if (threadIdx.x == 0) {
    uint32_t k0 = 0u, k1 = 42u, a, b;
    tf2x32(k0, k1, 0u, 0u, a, b); k0 = a; k1 = b;
    for (int i = 0; i < t; i++) { tf2x32(k0, k1, 0u, 0u, a, b); k0 = a; k1 = b; }
    tf2x32(k0, k1, 0u, 1u, a, b); sk0 = a; sk1 = b;
  }
  __syncthreads();
  const float TINY = 1.17549435e-38f;
  uint32_t s0 = sk0, s1 = sk1;
  for (int i = threadIdx.x; i < 6400; i += blockDim.x) {
    uint32_t o0, o1;
    tf2x32(s0, s1, 0u, (uint32_t)i, o0, o1);
    uint32_t bits = o0 ^ o1;
    float f = __uint_as_float((bits >> 9) | 0x3f800000u) - 1.0f;
    float u = fmaxf(TINY, f + TINY);
    g_gum[t * 6400 + i] = -logf(-logf(u));
  }
}

__device__ __forceinline__ float sigm(float x) { return 1.f / (1.f + expf(-x)); }

// ---------------- cluster-of-2 decoder v3: 384 thr, task-split, 2 syncs/step ----
// smem float offsets (floats):
#define SOF_WH0   0        // float4[6144]  Wh0 half (resident)
#define SOF_WP1R  24576    // float4[5376]  Wi1 half, kk 0..27 (resident)
#define SOF_YC    46080    // [100][65]     Y column-split (local 64 k's)
#define SOF_H0B   52580    // float2[2][128]
#define SOF_H1B   53092    // float2[2][128]
#define SOF_GI2   53604    // float2[192]   gi0 staging
#define SOF_GH2   53988    // float2[192]   L0 gh output
#define SOF_GH1C  54372    // float2[192]   gh1 output
#define SOF_GIP   54756    // float2[384]   gi1 partials
#define SOF_PL    55524    // float2[2][100] logit partials
#define SOF_LS    55924    // [100]
#define SOF_LG    56024    // [100]
#define SOF_YSA   56124    // [100]
#define SOF_SHI   56224    // int[2]
#define SOF_RED   56228    // [4]
#define SOF_SOLS  56232    // int[100]
#define SOF_SOLG  56332    // int[100]
#define DEC3_FLOATS 56436
__global__ void __cluster_dims__(2, 1, 1) __launch_bounds__(384, 1) k_decode(
    const float* __restrict__ dis, const float* __restrict__ bih,
    const float* __restrict__ bhh, float* __restrict__ out) {
  extern __shared__ float sm[];
  const int tid = threadIdx.x;
  const int b = blockIdx.x >> 1;
  const uint32_t rank = ctarank();
  const uint32_t peer = rank ^ 1u;
  const int lane = tid & 31, wrp = tid >> 5;
  const bool isA = tid < 192;
  const int c = isA ? tid : tid - 192;
  const int col = ((c >> 6) << 7) + ((int)rank << 6) + (c & 63);

  float4* wh0s = (float4*)(sm + SOF_WH0);
  float4* wp1r = (float4*)(sm + SOF_WP1R);
  float*  yc   = sm + SOF_YC;
  float2* gi2  = (float2*)(sm + SOF_GI2);
  float2* gh2  = (float2*)(sm + SOF_GH2);
  float2* gh1c = (float2*)(sm + SOF_GH1C);
  float2* gip  = (float2*)(sm + SOF_GIP);
  float2* pl   = (float2*)(sm + SOF_PL);
  float*  ls   = sm + SOF_LS;
  float*  lg   = sm + SOF_LG;
  float*  ysA  = sm + SOF_YSA;
  int*    shi  = (int*)(sm + SOF_SHI);
  float*  red  = sm + SOF_RED;
  int*    solS = (int*)(sm + SOF_SOLS);
  int*    solG = (int*)(sm + SOF_SOLG);

  const uint32_t sbase = smem_u32(sm);
  const float4* wp1g = g_wpk12 + ((int)rank * 2) * 6144;       // Wi1 half
  const float4* wp2g = g_wpk12 + ((int)rank * 2 + 1) * 6144;   // Wh1 half (streamed)

  // ---------------- prologue ----------------
  {
    const float4* w0src = g_wpk0 + rank * 6144;
    for (int i = tid; i < 6144; i += 384) wh0s[i] = w0src[i];
    for (int i = tid; i < 5376; i += 384) wp1r[i] = wp1g[i];
    for (int i = tid; i < 6400; i += 384) {
      int row = i >> 6, kk = i & 63;
      yc[row * 65 + kk] = g_y[b * 12800 + row * 128 + (int)rank * 64 + kk];
    }
    float2* h0z = (float2*)(sm + SOF_H0B);
    float2* h1z = (float2*)(sm + SOF_H1B);
    if (tid < 256) { h0z[tid] = make_float2(0.f, 0.f); h1z[tid] = make_float2(0.f, 0.f); }
    if (tid == 0) { solS[0] = 0; solG[0] = 0; red[2] = 0.f; red[3] = 0.f; }
  }
  float bh0_r = 0.f, bi1_r = 0.f, bh1_r = 0.f;
  if (isA) { bh0_r = bhh[col]; bi1_r = bih[384 + col]; }
  else     { bh1_r = bhh[384 + col]; }
  int cur_s = 0, cur_g = 0;
  __syncthreads();
  CSYNC();

  for (int t = 0; t < 99; t++) {
    const int p = t & 1;
    // ---- ph1: early loads ----
    float gum_r = 0.f;
    if (tid < 100) gum_r = __ldg(&g_gum[t * 6400 + b * 100 + tid]);
    float gi_s = 0.f, gi_g = 0.f;
    float4 wst0, wst1, wst2, wst3;   // streamed Wi1 tail (kk 28..31), B threads
    if (isA) {
      gi_s = __ldg(&g_gi0[(b * 100 + cur_s) * 384 + col]);
      gi_g = __ldg(&g_gi0[(b * 100 + cur_g) * 384 + col]);
    } else {
      wst0 = __ldg(&wp1g[28 * 192 + c]);
      wst1 = __ldg(&wp1g[29 * 192 + c]);
      wst2 = __ldg(&wp1g[30 * 192 + c]);
      wst3 = __ldg(&wp1g[31 * 192 + c]);
    }

    // ---- ph2: parallel gemvs (A: layer0 from smem, B: gh1 streamed) ----
    if (isA) {
      float as = bh0_r, ag = bh0_r;
      const float4* h0p = (const float4*)(sm + SOF_H0B + p * 256);
#pragma unroll 16
      for (int kk = 0; kk < 32; kk++) {
        float4 w  = wh0s[kk * 192 + c];
        float4 ha = h0p[2 * kk], hb = h0p[2 * kk + 1];
        as = fmaf(ha.x, w.x, as); ag = fmaf(ha.y, w.x, ag);
        as = fmaf(ha.z, w.y, as); ag = fmaf(ha.w, w.y, ag);
        as = fmaf(hb.x, w.z, as); ag = fmaf(hb.y, w.z, ag);
        as = fmaf(hb.z, w.w, as); ag = fmaf(hb.w, w.w, ag);
      }
      gh2[c] = make_float2(as, ag);
      gi2[c] = make_float2(gi_s, gi_g);
    } else {
      float ghs = bh1_r, ghg = bh1_r;
      const float4* h1p = (const float4*)(sm + SOF_H1B + p * 256);
#pragma unroll 16
      for (int kk = 0; kk < 32; kk++) {
        float4 w  = __ldg(&wp2g[kk * 192 + c]);
        float4 ca = h1p[2 * kk], cb = h1p[2 * kk + 1];
        ghs = fmaf(ca.x, w.x, ghs); ghg = fmaf(ca.y, w.x, ghg);
        ghs = fmaf(ca.z, w.y, ghs); ghg = fmaf(ca.w, w.y, ghg);
        ghs = fmaf(cb.x, w.z, ghs); ghg = fmaf(cb.y, w.z, ghg);
        ghs = fmaf(cb.z, w.w, ghs); ghg = fmaf(cb.w, w.w, ghg);
      }
      gh1c[c] = make_float2(ghs, ghg);
    }
    __syncthreads();

    // ---- gates#1 (tid<64): h0_new local half + peer store ----
    if (tid < 64) {
      int j = ((int)rank << 6) + tid;
      float2 ir = gi2[tid], iz = gi2[tid + 64], in_ = gi2[tid + 128];
      float2 hr = gh2[tid], hz = gh2[tid + 64], hn  = gh2[tid + 128];
      float2 hp = ((const float2*)(sm + SOF_H0B + p * 256))[j];
      float r0 = sigm(ir.x + hr.x), z0 = sigm(iz.x + hz.x), n0 = tanhf(in_.x + r0 * hn.x);
      float r1 = sigm(ir.y + hr.y), z1 = sigm(iz.y + hz.y), n1 = tanhf(in_.y + r1 * hn.y);
      float2 hv = make_float2((1.f - z0) * n0 + z0 * hp.x, (1.f - z1) * n1 + z1 * hp.y);
      ((float2*)(sm + SOF_H0B + (1 - p) * 256))[j] = hv;
      uint32_t addr = sbase + (((uint32_t)SOF_H0B + (uint32_t)(1 - p) * 256u + (uint32_t)j * 2u) << 2);
      peer_st_f2(addr, peer, hv.x, hv.y);
    }
    CSYNC();   // S1: full h0_new everywhere

    // ---- ph5: gi1 gemv, k-split across all 384 threads (chain 64) ----
    {
      const int kh = isA ? 0 : 1;
      float gis = isA ? bi1_r : 0.f;
      float gig = gis;
      const float4* h0n = (const float4*)(sm + SOF_H0B + (1 - p) * 256);
#pragma unroll 16
      for (int u = 0; u < 16; u++) {
        int kk = kh * 16 + u;
        float4 wi;
        if (kk < 28) wi = wp1r[kk * 192 + c];
        else wi = (kk == 28) ? wst0 : (kk == 29) ? wst1 : (kk == 30) ? wst2 : wst3;
        float4 ha = h0n[2 * kk], hb = h0n[2 * kk + 1];
        gis = fmaf(ha.x, wi.x, gis); gig = fmaf(ha.y, wi.x, gig);
        gis = fmaf(ha.z, wi.y, gis); gig = fmaf(ha.w, wi.y, gig);
        gis = fmaf(hb.x, wi.z, gis); gig = fmaf(hb.y, wi.z, gig);
        gis = fmaf(hb.z, wi.w, gis); gig = fmaf(hb.w, wi.w, gig);
      }
      gip[kh * 192 + c] = make_float2(gis, gig);
    }
    __syncthreads();

    // ---- gates#2 (tid<64): h1_new local half + peer store ----
    if (tid < 64) {
      int j = ((int)rank << 6) + tid;
      float2 iA = gip[tid],       iB = gip[192 + tid];
      float2 zA = gip[tid + 64],  zB = gip[256 + tid];
      float2 nA = gip[tid + 128], nB = gip[320 + tid];
      float2 ir = make_float2(iA.x + iB.x, iA.y + iB.y);
      float2 iz = make_float2(zA.x + zB.x, zA.y + zB.y);
      float2 in_ = make_float2(nA.x + nB.x, nA.y + nB.y);
      float2 hr = gh1c[tid], hz = gh1c[tid + 64], hn = gh1c[tid + 128];
      float2 hp = ((const float2*)(sm + SOF_H1B + p * 256))[j];
      float r0 = sigm(ir.x + hr.x), z0 = sigm(iz.x + hz.x), n0 = tanhf(in_.x + r0 * hn.x);
      float r1 = sigm(ir.y + hr.y), z1 = sigm(iz.y + hz.y), n1 = tanhf(in_.y + r1 * hn.y);
      float2 hv = make_float2((1.f - z0) * n0 + z0 * hp.x, (1.f - z1) * n1 + z1 * hp.y);
      ((float2*)(sm + SOF_H1B + (1 - p) * 256))[j] = hv;
      uint32_t addr = sbase + (((uint32_t)SOF_H1B + (uint32_t)(1 - p) * 256u + (uint32_t)j * 2u) << 2);
      peer_st_f2(addr, peer, hv.x, hv.y);
    }
    __syncthreads();   // local h1 half visible for logit partials

    // ---- ph7: logit partials over LOCAL 64 k's, all 100 rows; exchange ----
    if (tid < 100) {
      const float2* h1loc = ((const float2*)(sm + SOF_H1B + (1 - p) * 256)) + (int)rank * 64;
      const float* yr = yc + tid * 65;
      float s0 = 0.f, s1 = 0.f, g0 = 0.f, g1 = 0.f;
#pragma unroll 16
      for (int kk = 0; kk < 64; kk += 2) {
        float2 ha = h1loc[kk], hb = h1loc[kk + 1];
        float ya = yr[kk], yb = yr[kk + 1];
        s0 = fmaf(ha.x, ya, s0); g0 = fmaf(ha.y, ya, g0);
        s1 = fmaf(hb.x, yb, s1); g1 = fmaf(hb.y, yb, g1);
      }
      float ssv = s0 + s1, ggv = g0 + g1;
      pl[(int)rank * 100 + tid] = make_float2(ssv, ggv);
      uint32_t addr = sbase + (((uint32_t)SOF_PL + ((uint32_t)rank * 100u + (uint32_t)tid) * 2u) << 2);
      peer_st_f2(addr, peer, ssv, ggv);
    }
    CSYNC();   // S2: h1_new + logit partials everywhere

    // ---- ph9: combine (both CTAs redundantly & identically) ----
    if (tid < 100) {
      float2 a = pl[tid], b2 = pl[100 + tid];
      float lsv = a.x + b2.x, lgv = a.y + b2.y;
      ls[tid] = lsv;
      ysA[tid] = lsv + gum_r;
      lg[tid] = lgv;
    }
    __syncthreads();
    if (wrp == 0) {
      float bv = -3.4e38f; int bi_ = 0;
#pragma unroll
      for (int r = 0; r < 4; r++) { int i = lane + 32 * r; if (i < 100) { float v = ysA[i]; if (v > bv) { bv = v; bi_ = i; } } }
#pragma unroll
      for (int o = 16; o > 0; o >>= 1) {
        float ov = __shfl_xor_sync(0xffffffffu, bv, o);
        int   oi = __shfl_xor_sync(0xffffffffu, bi_, o);
        if (ov > bv || (ov == bv && oi < bi_)) { bv = ov; bi_ = oi; }
      }
      if (lane == 0) shi[0] = bi_;
    } else if (wrp == 1) {
      float bv = -3.4e38f; int bi_ = 0;
#pragma unroll
      for (int r = 0; r < 4; r++) { int i = lane + 32 * r; if (i < 100) { float v = lg[i]; if (v > bv) { bv = v; bi_ = i; } } }
#pragma unroll
      for (int o = 16; o > 0; o >>= 1) {
        float ov = __shfl_xor_sync(0xffffffffu, bv, o);
        int   oi = __shfl_xor_sync(0xffffffffu, bi_, o);
        if (ov > bv || (ov == bv && oi < bi_)) { bv = ov; bi_ = oi; }
      }
      if (lane == 0) shi[1] = bi_;
    } else if (wrp == 2) {
      float s = 0.f;
#pragma unroll
      for (int r = 0; r < 4; r++) { int i = lane + 32 * r; if (i < 100) s += expf(ls[i]); }
#pragma unroll
      for (int o = 16; o > 0; o >>= 1) s += __shfl_xor_sync(0xffffffffu, s, o);
      if (lane == 0) red[1] = s;
    }
    __syncthreads();
    cur_s = shi[0];
    cur_g = shi[1];
    if (tid == 0) {
      solS[t + 1] = cur_s;
      solG[t + 1] = cur_g;
      if (rank == 0) out[OFF_LOGP + b * 99 + t] = ls[cur_s] - logf(red[1]);
    }
    __syncthreads();
  }

  CSYNC();
  if (rank == 0) {
    if (tid < 99) {
      atomicAdd(&red[2], dis[b * 10000 + solS[tid] * 100 + solS[tid + 1]]);
      atomicAdd(&red[3], dis[b * 10000 + solG[tid] * 100 + solG[tid + 1]]);
    }
    for (int i = tid; i < 100; i += 384) g_solg[b * 100 + i] = solG[i];
    __syncthreads();
    if (tid == 0) { out[OFF_SD + b] = red[2]; out[OFF_GD + b] = red[3]; }
  }
}

// ---------------- predict_matrix fused ----------------
__global__ void k_pred(const float* __restrict__ dis, const float* __restrict__ We,
                       const float* __restrict__ be, const float* __restrict__ Wc,
                       const float* __restrict__ bc, float* __restrict__ out) {
  int lane = threadIdx.x & 31;
  int gw = (blockIdx.x * blockDim.x + threadIdx.x) >> 5;
  int nw = (gridDim.x * blockDim.x) >> 5;
  float we[4], bee[4], wc0[4], wc1[4];
#pragma unroll
  for (int u = 0; u < 4; u++) {
    int k = lane * 4 + u;
    we[u] = We[k]; bee[u] = be[k]; wc0[u] = Wc[k * 2]; wc1[u] = Wc[k * 2 + 1];
  }
  float bc0 = bc[0], bc1 = bc[1];
  for (int p = gw; p < 640000; p += nw) {
    float d = dis[p];
    float y0 = 0.f, y1 = 0.f;
#pragma unroll
    for (int u = 0; u < 4; u++) {
      float e = fmaxf(fmaf(d, we[u], bee[u]), 0.f);
      y0 = fmaf(e, wc0[u], y0); y1 = fmaf(e, wc1[u], y1);
    }
#pragma unroll
    for (int o = 16; o > 0; o >>= 1) {
      y0 += __shfl_xor_sync(0xffffffffu, y0, o);
      y1 += __shfl_xor_sync(0xffffffffu, y1, o);
    }
    if (lane == 0) {
      y0 += bc0; y1 += bc1;
      float m = fmaxf(y0, y1);
      float e0 = expf(y0 - m), e1 = expf(y1 - m), s = e0 + e1;
      out[OFF_PRED + p * 2]     = e0 / s;
      out[OFF_PRED + p * 2 + 1] = e1 / s;
    }
  }
}

__global__ void k_gzero(float* __restrict__ out) {
  int idx = blockIdx.x * blockDim.x + threadIdx.x;
  if (idx < 640000) out[OFF_GSOL + idx] = 0.f;
}

__global__ void k_gset(float* __restrict__ out) {
  int b = blockIdx.x, t = threadIdx.x;
  if (t < 99) {
    int u = g_solg[b * 100 + t], v = g_solg[b * 100 + t + 1];
    out[OFF_GSOL + b * 10000 + u * 100 + v] = 1.0f;
  }
}

extern "C" void kernel_launch(void* const* d_in, const int* in_sizes, int n_in,
                              void* d_out, int out_size) {
  const float* node   = (const float*)d_in[0];
  const float* demand = (const float*)d_in[1];
  const float* dis    = (const float*)d_in[2];
  const float* Wn0    = (const float*)d_in[3];
  const float* bn0    = (const float*)d_in[4];
  const float* Ws     = (const float*)d_in[5];
  const float* Wngh   = (const float*)d_in[6];
  const float* We     = (const float*)d_in[7];
  const float* be     = (const float*)d_in[8];
  const float* Wih    = (const float*)d_in[9];
  const float* Whh    = (const float*)d_in[10];
  const float* bih    = (const float*)d_in[11];
  const float* bhh    = (const float*)d_in[12];
  const float* Wq     = (const float*)d_in[13];
  const float* Wc     = (const float*)d_in[14];
  const float* bc     = (const float*)d_in[15];
  float* out = (float*)d_out;

  cudaFuncSetAttribute(k_aggr,   cudaFuncAttributeMaxDynamicSharedMemorySize, AGGR2_SMEM);
  cudaFuncSetAttribute(k_y,      cudaFuncAttributeMaxDynamicSharedMemorySize, Y_SMEM);
  cudaFuncSetAttribute(k_decode, cudaFuncAttributeMaxDynamicSharedMemorySize, DEC3_FLOATS * 4);

  k_h0<<<3200, 256>>>(node, demand, Wn0, bn0);
  k_softA<<<1600, 128>>>(dis);
  int src = 0;
  for (int l = 0; l < 3; l++) {
    k_gemm2<<<400, 128>>>(src, Ws + l * 16384, Wngh + l * 16384);
    int dst = 1 - src;
    k_aggr<<<dim3(64, 4), 512, AGGR2_SMEM>>>(dst);
    src = dst;
  }
  // final h in g_buf1
  k_gi0<<<800, 384>>>(Wih, bih);
  k_y<<<800, 128, Y_SMEM>>>(Wq);
  k_pack2<<<576, 256>>>(Wih, Whh);
  k_gumbel<<<99, 256>>>();
  k_decode<<<128, 384, DEC3_FLOATS * 4>>>(dis, bih, bhh, out);
  k_pred<<<1280, 256>>>(dis, We, be, Wc, bc, out);
  k_gzero<<<2500, 256>>>(out);
  k_gset<<<64, 128>>>(out);
}